// round 6
// baseline (speedup 1.0000x reference)
#include <cuda_runtime.h>
#include <math.h>
#include <stdint.h>

// Problem dims
#define L_  8
#define B_  8
#define S_  2048
#define D_  1024
#define H_  16
#define DH_ 64
#define F_  4096

// ---------------------------------------------------------------------------
// Scratch (__device__ globals; allocation-guard-safe)
// ---------------------------------------------------------------------------
__device__ float g_h   [(size_t)B_ * S_ * D_];
__device__ float g_q   [(size_t)B_ * S_ * D_];
__device__ float g_k   [(size_t)B_ * S_ * D_];
__device__ float g_v   [(size_t)B_ * S_ * D_];
__device__ float g_attn[(size_t)B_ * S_ * D_];
__device__ float g_ffn [(size_t)B_ * S_ * F_];
// Transposed + tf32-rounded weights: Wt[l][n][k]
__device__ float g_WqT[(size_t)L_ * D_ * D_];
__device__ float g_WkT[(size_t)L_ * D_ * D_];
__device__ float g_WvT[(size_t)L_ * D_ * D_];
__device__ float g_WoT[(size_t)L_ * D_ * D_];
__device__ float g_W1T[(size_t)L_ * D_ * F_];
__device__ float g_W2T[(size_t)L_ * F_ * D_];

// ---------------------------------------------------------------------------
// Helpers (baseline PTX only — no 'a'-suffix accel features)
// ---------------------------------------------------------------------------
__device__ __forceinline__ uint32_t smem_u32(const void* p) {
    uint32_t a;
    asm("{ .reg .u64 t; cvta.to.shared.u64 t, %1; cvt.u32.u64 %0, t; }"
        : "=r"(a) : "l"(p));
    return a;
}

__device__ __forceinline__ float tf32r(float x) {   // round-to-nearest tf32
    uint32_t u;
    asm("cvt.rna.tf32.f32 %0, %1;" : "=r"(u) : "f"(x));
    return __uint_as_float(u);
}

#define SMEM_SWZ128(o) ((o) ^ (((o) >> 3) & 0x70))

#define CP_ASYNC16(dst_u32, src_ptr) \
    asm volatile("cp.async.cg.shared.global [%0], [%1], 16;" \
                 :: "r"(dst_u32), "l"(src_ptr))
#define CP_ASYNC_COMMIT() asm volatile("cp.async.commit_group;" ::: "memory")
#define CP_ASYNC_WAIT1()  asm volatile("cp.async.wait_group 1;" ::: "memory")
#define CP_ASYNC_WAIT0()  asm volatile("cp.async.wait_group 0;" ::: "memory")

__device__ __forceinline__ void ldsm_x4(uint32_t (&r)[4], uint32_t addr) {
    asm volatile("ldmatrix.sync.aligned.m8n8.x4.shared.b16 {%0,%1,%2,%3}, [%4];"
                 : "=r"(r[0]), "=r"(r[1]), "=r"(r[2]), "=r"(r[3]) : "r"(addr));
}

__device__ __forceinline__ void mma_tf32(float (&d)[4],
                                         const uint32_t (&a)[4],
                                         uint32_t b0, uint32_t b1) {
    asm volatile(
        "mma.sync.aligned.m16n8k8.row.col.f32.tf32.tf32.f32 "
        "{%0,%1,%2,%3}, {%4,%5,%6,%7}, {%8,%9}, {%0,%1,%2,%3};"
        : "+f"(d[0]), "+f"(d[1]), "+f"(d[2]), "+f"(d[3])
        : "r"(a[0]), "r"(a[1]), "r"(a[2]), "r"(a[3]), "r"(b0), "r"(b1));
}

// ---------------------------------------------------------------------------
// GELU (tanh approx — matches jax.nn.gelu default)
// ---------------------------------------------------------------------------
__device__ __forceinline__ float gelu_f(float x)
{
    float t = 0.7978845608028654f * (x + 0.044715f * x * x * x);
    float th;
    asm("tanh.approx.f32 %0, %1;" : "=f"(th) : "f"(t));
    return 0.5f * x * (1.0f + th);
}

// ---------------------------------------------------------------------------
// Weight transpose + tf32 RN round: W[l][K][N] -> Wt[l][N][K]
// ---------------------------------------------------------------------------
__global__ __launch_bounds__(256) void transpose_round_kernel(
    const float* __restrict__ W, float* __restrict__ Wt, int Kd, int Nd)
{
    __shared__ float t[32][33];
    int l  = blockIdx.z;
    int n0 = blockIdx.x * 32;
    int k0 = blockIdx.y * 32;
    const float* Wl  = W  + (size_t)l * Kd * Nd;
    float*       Wtl = Wt + (size_t)l * Nd * Kd;
    int c = threadIdx.x, r0 = threadIdx.y;
    #pragma unroll
    for (int i = 0; i < 4; i++) {
        int r = r0 + i * 8;
        t[r][c] = Wl[(size_t)(k0 + r) * Nd + n0 + c];
    }
    __syncthreads();
    #pragma unroll
    for (int i = 0; i < 4; i++) {
        int r = r0 + i * 8;
        Wtl[(size_t)(n0 + r) * Kd + k0 + c] = tf32r(t[c][r]);
    }
}

// ---------------------------------------------------------------------------
// LayerNorm (rounds output to tf32 — feeds tensor-core GEMMs)
// ---------------------------------------------------------------------------
__global__ __launch_bounds__(256) void ln_kernel(
    const float* __restrict__ X,
    const float* __restrict__ sall, const float* __restrict__ ball,
    const int* __restrict__ lidx, float* __restrict__ Y)
{
    int row = blockIdx.x;
    int b   = row / S_;
    int tid = threadIdx.x;

    float4 xv = ((const float4*)(X + (size_t)row * D_))[tid];
    float s  = xv.x + xv.y + xv.z + xv.w;
    float ss = xv.x*xv.x + xv.y*xv.y + xv.z*xv.z + xv.w*xv.w;
    #pragma unroll
    for (int o = 16; o > 0; o >>= 1) {
        s  += __shfl_xor_sync(0xffffffffu, s,  o);
        ss += __shfl_xor_sync(0xffffffffu, ss, o);
    }
    __shared__ float rs[8], rss[8], mv[2];
    int wid = tid >> 5, lane = tid & 31;
    if (lane == 0) { rs[wid] = s; rss[wid] = ss; }
    __syncthreads();
    if (tid == 0) {
        float a = 0.f, c = 0.f;
        #pragma unroll
        for (int w = 0; w < 8; w++) { a += rs[w]; c += rss[w]; }
        float mean = a * (1.0f / D_);
        float var  = c * (1.0f / D_) - mean * mean;
        mv[0] = mean; mv[1] = rsqrtf(var + 1e-5f);
    }
    __syncthreads();
    float mean = mv[0], rstd = mv[1];

    int li = lidx[b];
    float4 sv = ((const float4*)(sall + (size_t)li * D_))[tid];
    float4 bv = ((const float4*)(ball + (size_t)li * D_))[tid];
    float4 o;
    o.x = tf32r((xv.x - mean) * rstd * sv.x + bv.x);
    o.y = tf32r((xv.y - mean) * rstd * sv.y + bv.y);
    o.z = tf32r((xv.z - mean) * rstd * sv.z + bv.z);
    o.w = tf32r((xv.w - mean) * rstd * sv.w + bv.w);
    ((float4*)(Y + (size_t)row * D_))[tid] = o;
}

// ---------------------------------------------------------------------------
// mma.sync tf32 GEMM: C[b] = A[b](MxK) @ Wt[lidx[b]](NxK)^T + bias
//                     (+GELU) (+residual) (+tf32 round on store)
// 128x128 tile, BK=32, 8 warps (2x4), warp tile 64x32 of m16n8k8.
// 3-stage cp.async ring, SW128 swizzle, ldmatrix fragment loads.
// ---------------------------------------------------------------------------
#define GEMM_SMEM (1024 + 3 * 32768)

template <int ACT, int RES, int RND>
__global__ __launch_bounds__(256, 2)
void gemm_mma(const float* __restrict__ A, const float* __restrict__ WT,
              const float* __restrict__ biasall, const int* __restrict__ lidx,
              const float* __restrict__ Res, float* __restrict__ C,
              int M, int K, int N)
{
    extern __shared__ __align__(16) char smraw[];
    uint32_t sbase = (smem_u32(smraw) + 1023u) & ~1023u;

    int tid  = threadIdx.x;
    int wid  = tid >> 5;
    int lane = tid & 31;
    int wm   = wid >> 2;      // 0..1
    int wn   = wid & 3;       // 0..3
    int b    = blockIdx.z;
    int li   = lidx[b];
    int row0 = blockIdx.y * 128;
    int col0 = blockIdx.x * 128;

    const float* Ag = A  + (size_t)b  * M * K + (size_t)row0 * K;
    const float* Bg = WT + (size_t)li * N * K + (size_t)col0 * K;

    float acc[4][4][4];
    #pragma unroll
    for (int i = 0; i < 4; i++)
        #pragma unroll
        for (int j = 0; j < 4; j++)
            #pragma unroll
            for (int q = 0; q < 4; q++) acc[i][j][q] = 0.f;

    // Per-thread cp.async slots: A and B tiles are each 128 rows x 128B.
    int lrow = tid >> 1;              // 0..127
    int lkb  = (tid & 1) * 64;        // 0 or 64 bytes; 2 chunks of 16B each... 
    // Simpler: 1024 16B-chunks per tile, 4 per thread.
    auto load_stage = [&](int kc, int stg) {
        uint32_t sA = sbase + (uint32_t)stg * 32768u;
        uint32_t sB = sA + 16384u;
        const float* Ak = Ag + kc * 32;
        const float* Bk = Bg + kc * 32;
        #pragma unroll
        for (int p = 0; p < 4; p++) {
            int idx = tid + p * 256;
            int r  = idx >> 3;
            int kb = (idx & 7) * 16;            // byte offset in row
            uint32_t sw = SMEM_SWZ128((uint32_t)(r * 128 + kb));
            CP_ASYNC16(sA + sw, Ak + (size_t)r * K + (kb >> 2));
            CP_ASYNC16(sB + sw, Bk + (size_t)r * K + (kb >> 2));
        }
        CP_ASYNC_COMMIT();
    };

    int nk = K >> 5;
    load_stage(0, 0);
    load_stage(1, 1);

    int lr = lane & 15;      // row-within-16 for ldmatrix addressing
    int lh = (lane >> 4) * 16;  // +16B for second k-half

    for (int i = 0; i < nk; i++) {
        if (i < nk - 2) CP_ASYNC_WAIT1(); else CP_ASYNC_WAIT0();
        __syncthreads();
        if (i + 2 < nk) load_stage(i + 2, (i + 2) % 3);

        uint32_t sA = sbase + (uint32_t)(i % 3) * 32768u;
        uint32_t sB = sA + 16384u;

        #pragma unroll
        for (int ks = 0; ks < 4; ks++) {
            uint32_t afr[4][4];
            uint32_t bfr[2][4];
            #pragma unroll
            for (int mf = 0; mf < 4; mf++) {
                uint32_t off = (uint32_t)((64 * wm + 16 * mf + lr) * 128
                                          + ks * 32 + lh);
                ldsm_x4(afr[mf], sA + SMEM_SWZ128(off));
            }
            #pragma unroll
            for (int bf = 0; bf < 2; bf++) {
                uint32_t off = (uint32_t)((32 * wn + 16 * bf + lr) * 128
                                          + ks * 32 + lh);
                ldsm_x4(bfr[bf], sB + SMEM_SWZ128(off));
            }
            // bfr[bf]: r0=b0(nf=2bf), r1=b0(nf=2bf+1), r2=b1(nf=2bf), r3=b1(nf=2bf+1)
            #pragma unroll
            for (int mf = 0; mf < 4; mf++)
                #pragma unroll
                for (int nf = 0; nf < 4; nf++)
                    mma_tf32(acc[mf][nf], afr[mf],
                             bfr[nf >> 1][nf & 1], bfr[nf >> 1][2 + (nf & 1)]);
        }
    }
    (void)lrow; (void)lkb;

    // Epilogue: c0,c1 at (row=qr, col=qc..qc+1), c2,c3 at row+8.
    int qr = lane >> 2;
    int qc = (lane & 3) * 2;
    const float* bp = biasall + (size_t)li * N;
    #pragma unroll
    for (int mf = 0; mf < 4; mf++) {
        int r = row0 + 64 * wm + 16 * mf + qr;
        #pragma unroll
        for (int nf = 0; nf < 4; nf++) {
            int cc = col0 + 32 * wn + 8 * nf + qc;
            #pragma unroll
            for (int half = 0; half < 2; half++) {
                int rr = r + half * 8;
                float v0 = acc[mf][nf][half * 2 + 0] + bp[cc + 0];
                float v1 = acc[mf][nf][half * 2 + 1] + bp[cc + 1];
                if (ACT) { v0 = gelu_f(v0); v1 = gelu_f(v1); }
                if (RES) {
                    const float* rp = Res + (size_t)b * M * N + (size_t)rr * N + cc;
                    v0 += rp[0]; v1 += rp[1];
                }
                if (RND) { v0 = tf32r(v0); v1 = tf32r(v1); }
                float2 o2 = make_float2(v0, v1);
                *(float2*)&C[(size_t)b * M * N + (size_t)rr * N + cc] = o2;
            }
        }
    }
}

// ---------------------------------------------------------------------------
// Flash attention (fp32 SIMT — unchanged from the passing R1 version,
// plus tf32-rounded output store since it feeds the Wo GEMM)
// ---------------------------------------------------------------------------
#define AT_SMEM_FLOATS (128*65 + 64*65 + 64*64 + 128*65)
#define AT_SMEM_BYTES  (AT_SMEM_FLOATS * 4)

__global__ __launch_bounds__(256) void attention_kernel(
    const float* __restrict__ Q, const float* __restrict__ K,
    const float* __restrict__ V, float* __restrict__ O)
{
    extern __shared__ float sm[];
    float* Qs = sm;
    float* Ks = Qs + 128 * 65;
    float* Vs = Ks + 64 * 65;
    float* Ps = Vs + 64 * 64;

    int q0 = blockIdx.x * 128;
    int hh = blockIdx.y;
    int b  = blockIdx.z;
    int tid = threadIdx.x;
    int tx  = tid & 15;
    int ty  = tid >> 4;

    size_t base = (size_t)b * S_ * D_ + (size_t)hh * DH_;

    for (int it = tid; it < 128 * 16; it += 256) {
        int r  = it >> 4;
        int c4 = (it & 15) * 4;
        float4 qv = *(const float4*)&Q[base + (size_t)(q0 + r) * D_ + c4];
        float* dst = &Qs[r * 65 + c4];
        dst[0] = qv.x * 0.125f; dst[1] = qv.y * 0.125f;
        dst[2] = qv.z * 0.125f; dst[3] = qv.w * 0.125f;
    }

    float m_run[8], l_run[8], oacc[8][4];
    #pragma unroll
    for (int i = 0; i < 8; i++) {
        m_run[i] = -1e30f; l_run[i] = 0.f;
        #pragma unroll
        for (int j = 0; j < 4; j++) oacc[i][j] = 0.f;
    }

    for (int t = 0; t < S_ / 64; t++) {
        int k0 = t * 64;
        for (int it = tid; it < 64 * 16; it += 256) {
            int r  = it >> 4;
            int c4 = (it & 15) * 4;
            float4 kv = *(const float4*)&K[base + (size_t)(k0 + r) * D_ + c4];
            float* dk = &Ks[r * 65 + c4];
            dk[0] = kv.x; dk[1] = kv.y; dk[2] = kv.z; dk[3] = kv.w;
            float4 vv = *(const float4*)&V[base + (size_t)(k0 + r) * D_ + c4];
            *(float4*)&Vs[r * 64 + c4] = vv;
        }
        __syncthreads();

        float sreg[8][4];
        #pragma unroll
        for (int i = 0; i < 8; i++)
            #pragma unroll
            for (int j = 0; j < 4; j++) sreg[i][j] = 0.f;

        #pragma unroll 8
        for (int k = 0; k < 64; k++) {
            float qv[8], kv[4];
            #pragma unroll
            for (int i = 0; i < 8; i++) qv[i] = Qs[(ty + 16 * i) * 65 + k];
            #pragma unroll
            for (int j = 0; j < 4; j++) kv[j] = Ks[(tx + 16 * j) * 65 + k];
            #pragma unroll
            for (int i = 0; i < 8; i++)
                #pragma unroll
                for (int j = 0; j < 4; j++)
                    sreg[i][j] += qv[i] * kv[j];
        }

        #pragma unroll
        for (int i = 0; i < 8; i++) {
            float mt = fmaxf(fmaxf(sreg[i][0], sreg[i][1]),
                             fmaxf(sreg[i][2], sreg[i][3]));
            #pragma unroll
            for (int o = 8; o > 0; o >>= 1)
                mt = fmaxf(mt, __shfl_xor_sync(0xffffffffu, mt, o));
            float mn   = fmaxf(m_run[i], mt);
            float corr = __expf(m_run[i] - mn);
            float ps = 0.f;
            #pragma unroll
            for (int j = 0; j < 4; j++) {
                float p = __expf(sreg[i][j] - mn);
                Ps[(ty + 16 * i) * 65 + tx + 16 * j] = p;
                ps += p;
            }
            #pragma unroll
            for (int o = 8; o > 0; o >>= 1)
                ps += __shfl_xor_sync(0xffffffffu, ps, o);
            l_run[i] = l_run[i] * corr + ps;
            m_run[i] = mn;
            #pragma unroll
            for (int j = 0; j < 4; j++) oacc[i][j] *= corr;
        }
        __syncthreads();

        #pragma unroll 8
        for (int c = 0; c < 64; c++) {
            float pv[8], vv[4];
            #pragma unroll
            for (int i = 0; i < 8; i++) pv[i] = Ps[(ty + 16 * i) * 65 + c];
            #pragma unroll
            for (int j = 0; j < 4; j++) vv[j] = Vs[c * 64 + tx + 16 * j];
            #pragma unroll
            for (int i = 0; i < 8; i++)
                #pragma unroll
                for (int j = 0; j < 4; j++)
                    oacc[i][j] += pv[i] * vv[j];
        }
        __syncthreads();
    }

    #pragma unroll
    for (int i = 0; i < 8; i++) {
        float inv = 1.0f / l_run[i];
        int r = q0 + ty + 16 * i;
        #pragma unroll
        for (int j = 0; j < 4; j++)
            O[base + (size_t)r * D_ + tx + 16 * j] = tf32r(oacc[i][j] * inv);
    }
}

// ---------------------------------------------------------------------------
// Launch
// ---------------------------------------------------------------------------
extern "C" void kernel_launch(void* const* d_in, const int* in_sizes, int n_in,
                              void* d_out, int out_size)
{
    (void)in_sizes; (void)n_in; (void)out_size;
    const float* x    = (const float*)d_in[0];
    const int*   lidx = (const int*)  d_in[1];
    const float* Wq = (const float*)d_in[2];  const float* bq = (const float*)d_in[3];
    const float* Wk = (const float*)d_in[4];  const float* bk = (const float*)d_in[5];
    const float* Wv = (const float*)d_in[6];  const float* bv = (const float*)d_in[7];
    const float* Wo = (const float*)d_in[8];  const float* bo = (const float*)d_in[9];
    const float* s1 = (const float*)d_in[10]; const float* b1n = (const float*)d_in[11];
    const float* s2 = (const float*)d_in[12]; const float* b2n = (const float*)d_in[13];
    const float* W1 = (const float*)d_in[14]; const float* bf1 = (const float*)d_in[15];
    const float* W2 = (const float*)d_in[16]; const float* bf2 = (const float*)d_in[17];
    float* out = (float*)d_out;

    float *h_, *q_, *k_, *v_, *at_, *ff_;
    float *wqT, *wkT, *wvT, *woT, *w1T, *w2T;
    cudaGetSymbolAddress((void**)&h_,  g_h);
    cudaGetSymbolAddress((void**)&q_,  g_q);
    cudaGetSymbolAddress((void**)&k_,  g_k);
    cudaGetSymbolAddress((void**)&v_,  g_v);
    cudaGetSymbolAddress((void**)&at_, g_attn);
    cudaGetSymbolAddress((void**)&ff_, g_ffn);
    cudaGetSymbolAddress((void**)&wqT, g_WqT);
    cudaGetSymbolAddress((void**)&wkT, g_WkT);
    cudaGetSymbolAddress((void**)&wvT, g_WvT);
    cudaGetSymbolAddress((void**)&woT, g_WoT);
    cudaGetSymbolAddress((void**)&w1T, g_W1T);
    cudaGetSymbolAddress((void**)&w2T, g_W2T);

    cudaFuncSetAttribute(attention_kernel,
                         cudaFuncAttributeMaxDynamicSharedMemorySize, AT_SMEM_BYTES);
    cudaFuncSetAttribute(gemm_mma<0,0,0>,
                         cudaFuncAttributeMaxDynamicSharedMemorySize, GEMM_SMEM);
    cudaFuncSetAttribute(gemm_mma<0,1,0>,
                         cudaFuncAttributeMaxDynamicSharedMemorySize, GEMM_SMEM);
    cudaFuncSetAttribute(gemm_mma<1,0,1>,
                         cudaFuncAttributeMaxDynamicSharedMemorySize, GEMM_SMEM);

    // Weight transpose + tf32 rounding
    dim3 tb(32, 8);
    transpose_round_kernel<<<dim3(D_/32, D_/32, L_), tb>>>(Wq, wqT, D_, D_);
    transpose_round_kernel<<<dim3(D_/32, D_/32, L_), tb>>>(Wk, wkT, D_, D_);
    transpose_round_kernel<<<dim3(D_/32, D_/32, L_), tb>>>(Wv, wvT, D_, D_);
    transpose_round_kernel<<<dim3(D_/32, D_/32, L_), tb>>>(Wo, woT, D_, D_);
    transpose_round_kernel<<<dim3(F_/32, D_/32, L_), tb>>>(W1, w1T, D_, F_);
    transpose_round_kernel<<<dim3(D_/32, F_/32, L_), tb>>>(W2, w2T, F_, D_);

    dim3 gD(D_ / 128, S_ / 128, B_);
    dim3 gF(F_ / 128, S_ / 128, B_);

    // LN1 -> h (tf32-rounded)
    ln_kernel<<<B_ * S_, 256>>>(x, s1, b1n, lidx, h_);
    // QKV (fp32 outputs for SIMT attention)
    gemm_mma<0,0,0><<<gD, 256, GEMM_SMEM>>>(h_, wqT, bq, lidx, nullptr, q_, S_, D_, D_);
    gemm_mma<0,0,0><<<gD, 256, GEMM_SMEM>>>(h_, wkT, bk, lidx, nullptr, k_, S_, D_, D_);
    gemm_mma<0,0,0><<<gD, 256, GEMM_SMEM>>>(h_, wvT, bv, lidx, nullptr, v_, S_, D_, D_);
    // Attention (tf32-rounded output -> Wo GEMM input)
    attention_kernel<<<dim3(S_ / 128, H_, B_), 256, AT_SMEM_BYTES>>>(q_, k_, v_, at_);
    // O-proj + residual(x) -> out
    gemm_mma<0,1,0><<<gD, 256, GEMM_SMEM>>>(at_, woT, bo, lidx, x, out, S_, D_, D_);
    // LN2 -> h (tf32-rounded)
    ln_kernel<<<B_ * S_, 256>>>(out, s2, b2n, lidx, h_);
    // FFN1 + GELU (tf32-rounded -> FFN2 input)
    gemm_mma<1,0,1><<<gF, 256, GEMM_SMEM>>>(h_, w1T, bf1, lidx, nullptr, ff_, S_, D_, F_);
    // FFN2 + residual(out) -> final
    gemm_mma<0,1,0><<<gD, 256, GEMM_SMEM>>>(ff_, w2T, bf2, lidx, out, out, S_, F_, D_);
}

// round 7
// speedup vs baseline: 1.7300x; 1.7300x over previous
#include <cuda_runtime.h>
#include <math.h>
#include <stdint.h>

// Problem dims
#define L_  8
#define B_  8
#define S_  2048
#define D_  1024
#define H_  16
#define DH_ 64
#define F_  4096

// ---------------------------------------------------------------------------
// Scratch (__device__ globals; allocation-guard-safe)
// ---------------------------------------------------------------------------
__device__ float g_h   [(size_t)B_ * S_ * D_];
__device__ float g_q   [(size_t)B_ * S_ * D_];
__device__ float g_k   [(size_t)B_ * S_ * D_];
__device__ float g_vT  [(size_t)B_ * H_ * DH_ * S_];   // V transposed per head
__device__ float g_attn[(size_t)B_ * S_ * D_];
__device__ float g_ffn [(size_t)B_ * S_ * F_];
// Transposed + tf32-rounded weights: Wt[l][n][k]
__device__ float g_WqT[(size_t)L_ * D_ * D_];
__device__ float g_WkT[(size_t)L_ * D_ * D_];
__device__ float g_WvT[(size_t)L_ * D_ * D_];
__device__ float g_WoT[(size_t)L_ * D_ * D_];
__device__ float g_W1T[(size_t)L_ * D_ * F_];
__device__ float g_W2T[(size_t)L_ * F_ * D_];

// ---------------------------------------------------------------------------
// Helpers (baseline PTX only — no 'a'-suffix accel features)
// ---------------------------------------------------------------------------
__device__ __forceinline__ uint32_t smem_u32(const void* p) {
    uint32_t a;
    asm("{ .reg .u64 t; cvta.to.shared.u64 t, %1; cvt.u32.u64 %0, t; }"
        : "=r"(a) : "l"(p));
    return a;
}

__device__ __forceinline__ float tf32r(float x) {   // round-to-nearest tf32
    uint32_t u;
    asm("cvt.rna.tf32.f32 %0, %1;" : "=r"(u) : "f"(x));
    return __uint_as_float(u);
}

#define SMEM_SWZ128(o) ((o) ^ (((o) >> 3) & 0x70))

#define CP_ASYNC16(dst_u32, src_ptr) \
    asm volatile("cp.async.cg.shared.global [%0], [%1], 16;" \
                 :: "r"(dst_u32), "l"(src_ptr))
#define CP_ASYNC_COMMIT() asm volatile("cp.async.commit_group;" ::: "memory")
#define CP_ASYNC_WAIT1()  asm volatile("cp.async.wait_group 1;" ::: "memory")
#define CP_ASYNC_WAIT0()  asm volatile("cp.async.wait_group 0;" ::: "memory")

__device__ __forceinline__ void ldsm_x4(uint32_t (&r)[4], uint32_t addr) {
    asm volatile("ldmatrix.sync.aligned.m8n8.x4.shared.b16 {%0,%1,%2,%3}, [%4];"
                 : "=r"(r[0]), "=r"(r[1]), "=r"(r[2]), "=r"(r[3]) : "r"(addr));
}

__device__ __forceinline__ void mma_tf32(float (&d)[4],
                                         const uint32_t (&a)[4],
                                         uint32_t b0, uint32_t b1) {
    asm volatile(
        "mma.sync.aligned.m16n8k8.row.col.f32.tf32.tf32.f32 "
        "{%0,%1,%2,%3}, {%4,%5,%6,%7}, {%8,%9}, {%0,%1,%2,%3};"
        : "+f"(d[0]), "+f"(d[1]), "+f"(d[2]), "+f"(d[3])
        : "r"(a[0]), "r"(a[1]), "r"(a[2]), "r"(a[3]), "r"(b0), "r"(b1));
}

// ---------------------------------------------------------------------------
// GELU (tanh approx — matches jax.nn.gelu default)
// ---------------------------------------------------------------------------
__device__ __forceinline__ float gelu_f(float x)
{
    float t = 0.7978845608028654f * (x + 0.044715f * x * x * x);
    float th;
    asm("tanh.approx.f32 %0, %1;" : "=f"(th) : "f"(t));
    return 0.5f * x * (1.0f + th);
}

// ---------------------------------------------------------------------------
// Weight transpose + tf32 RN round: W[l][K][N] -> Wt[l][N][K]
// ---------------------------------------------------------------------------
__global__ __launch_bounds__(256) void transpose_round_kernel(
    const float* __restrict__ W, float* __restrict__ Wt, int Kd, int Nd)
{
    __shared__ float t[32][33];
    int l  = blockIdx.z;
    int n0 = blockIdx.x * 32;
    int k0 = blockIdx.y * 32;
    const float* Wl  = W  + (size_t)l * Kd * Nd;
    float*       Wtl = Wt + (size_t)l * Nd * Kd;
    int c = threadIdx.x, r0 = threadIdx.y;
    #pragma unroll
    for (int i = 0; i < 4; i++) {
        int r = r0 + i * 8;
        t[r][c] = Wl[(size_t)(k0 + r) * Nd + n0 + c];
    }
    __syncthreads();
    #pragma unroll
    for (int i = 0; i < 4; i++) {
        int r = r0 + i * 8;
        Wtl[(size_t)(n0 + r) * Kd + k0 + c] = tf32r(t[c][r]);
    }
}

// ---------------------------------------------------------------------------
// LayerNorm (rounds output to tf32 — feeds tensor-core GEMMs)
// ---------------------------------------------------------------------------
__global__ __launch_bounds__(256) void ln_kernel(
    const float* __restrict__ X,
    const float* __restrict__ sall, const float* __restrict__ ball,
    const int* __restrict__ lidx, float* __restrict__ Y)
{
    int row = blockIdx.x;
    int b   = row / S_;
    int tid = threadIdx.x;

    float4 xv = ((const float4*)(X + (size_t)row * D_))[tid];
    float s  = xv.x + xv.y + xv.z + xv.w;
    float ss = xv.x*xv.x + xv.y*xv.y + xv.z*xv.z + xv.w*xv.w;
    #pragma unroll
    for (int o = 16; o > 0; o >>= 1) {
        s  += __shfl_xor_sync(0xffffffffu, s,  o);
        ss += __shfl_xor_sync(0xffffffffu, ss, o);
    }
    __shared__ float rs[8], rss[8], mv[2];
    int wid = tid >> 5, lane = tid & 31;
    if (lane == 0) { rs[wid] = s; rss[wid] = ss; }
    __syncthreads();
    if (tid == 0) {
        float a = 0.f, c = 0.f;
        #pragma unroll
        for (int w = 0; w < 8; w++) { a += rs[w]; c += rss[w]; }
        float mean = a * (1.0f / D_);
        float var  = c * (1.0f / D_) - mean * mean;
        mv[0] = mean; mv[1] = rsqrtf(var + 1e-5f);
    }
    __syncthreads();
    float mean = mv[0], rstd = mv[1];

    int li = lidx[b];
    float4 sv = ((const float4*)(sall + (size_t)li * D_))[tid];
    float4 bv = ((const float4*)(ball + (size_t)li * D_))[tid];
    float4 o;
    o.x = tf32r((xv.x - mean) * rstd * sv.x + bv.x);
    o.y = tf32r((xv.y - mean) * rstd * sv.y + bv.y);
    o.z = tf32r((xv.z - mean) * rstd * sv.z + bv.z);
    o.w = tf32r((xv.w - mean) * rstd * sv.w + bv.w);
    ((float4*)(Y + (size_t)row * D_))[tid] = o;
}

// ---------------------------------------------------------------------------
// mma.sync tf32 GEMM: C[b] = A[b](MxK) @ Wt[lidx[b]](NxK)^T + bias
//   (+GELU) (+residual) (+tf32 round) (TRNS: write per-head-transposed V^T)
// 128x128 tile, BK=32, 8 warps (2x4), warp tile 64x32 of m16n8k8.
// 3-stage cp.async ring, SW128 swizzle, ldmatrix fragment loads.
// ---------------------------------------------------------------------------
#define GEMM_SMEM (1024 + 3 * 32768)

template <int ACT, int RES, int RND, int TRNS>
__global__ __launch_bounds__(256, 2)
void gemm_mma(const float* __restrict__ A, const float* __restrict__ WT,
              const float* __restrict__ biasall, const int* __restrict__ lidx,
              const float* __restrict__ Res, float* __restrict__ C,
              int M, int K, int N)
{
    extern __shared__ __align__(16) char smraw[];
    uint32_t sbase = (smem_u32(smraw) + 1023u) & ~1023u;

    int tid  = threadIdx.x;
    int wid  = tid >> 5;
    int lane = tid & 31;
    int wm   = wid >> 2;      // 0..1
    int wn   = wid & 3;       // 0..3
    int b    = blockIdx.z;
    int li   = lidx[b];
    int row0 = blockIdx.y * 128;
    int col0 = blockIdx.x * 128;

    const float* Ag = A  + (size_t)b  * M * K + (size_t)row0 * K;
    const float* Bg = WT + (size_t)li * N * K + (size_t)col0 * K;

    float acc[4][4][4];
    #pragma unroll
    for (int i = 0; i < 4; i++)
        #pragma unroll
        for (int j = 0; j < 4; j++)
            #pragma unroll
            for (int q = 0; q < 4; q++) acc[i][j][q] = 0.f;

    auto load_stage = [&](int kc, int stg) {
        uint32_t sA = sbase + (uint32_t)stg * 32768u;
        uint32_t sB = sA + 16384u;
        const float* Ak = Ag + kc * 32;
        const float* Bk = Bg + kc * 32;
        #pragma unroll
        for (int p = 0; p < 4; p++) {
            int idx = tid + p * 256;
            int r  = idx >> 3;
            int kb = (idx & 7) * 16;            // byte offset in row
            uint32_t sw = SMEM_SWZ128((uint32_t)(r * 128 + kb));
            CP_ASYNC16(sA + sw, Ak + (size_t)r * K + (kb >> 2));
            CP_ASYNC16(sB + sw, Bk + (size_t)r * K + (kb >> 2));
        }
        CP_ASYNC_COMMIT();
    };

    int nk = K >> 5;
    load_stage(0, 0);
    load_stage(1, 1);

    int lr = lane & 15;
    int lh = (lane >> 4) * 16;

    for (int i = 0; i < nk; i++) {
        if (i < nk - 2) CP_ASYNC_WAIT1(); else CP_ASYNC_WAIT0();
        __syncthreads();
        if (i + 2 < nk) load_stage(i + 2, (i + 2) % 3);

        uint32_t sA = sbase + (uint32_t)(i % 3) * 32768u;
        uint32_t sB = sA + 16384u;

        #pragma unroll
        for (int ks = 0; ks < 4; ks++) {
            uint32_t afr[4][4];
            uint32_t bfr[2][4];
            #pragma unroll
            for (int mf = 0; mf < 4; mf++) {
                uint32_t off = (uint32_t)((64 * wm + 16 * mf + lr) * 128
                                          + ks * 32 + lh);
                ldsm_x4(afr[mf], sA + SMEM_SWZ128(off));
            }
            #pragma unroll
            for (int bf = 0; bf < 2; bf++) {
                uint32_t off = (uint32_t)((32 * wn + 16 * bf + lr) * 128
                                          + ks * 32 + lh);
                ldsm_x4(bfr[bf], sB + SMEM_SWZ128(off));
            }
            #pragma unroll
            for (int mf = 0; mf < 4; mf++)
                #pragma unroll
                for (int nf = 0; nf < 4; nf++)
                    mma_tf32(acc[mf][nf], afr[mf],
                             bfr[nf >> 1][nf & 1], bfr[nf >> 1][2 + (nf & 1)]);
        }
    }

    // Epilogue
    int qr = lane >> 2;
    int qc = (lane & 3) * 2;
    const float* bp = biasall + (size_t)li * N;
    #pragma unroll
    for (int mf = 0; mf < 4; mf++) {
        int r = row0 + 64 * wm + 16 * mf + qr;
        #pragma unroll
        for (int nf = 0; nf < 4; nf++) {
            int cc = col0 + 32 * wn + 8 * nf + qc;
            #pragma unroll
            for (int half = 0; half < 2; half++) {
                int rr = r + half * 8;
                float v0 = acc[mf][nf][half * 2 + 0] + bp[cc + 0];
                float v1 = acc[mf][nf][half * 2 + 1] + bp[cc + 1];
                if (ACT) { v0 = gelu_f(v0); v1 = gelu_f(v1); }
                if (RES) {
                    const float* rp = Res + (size_t)b * M * N + (size_t)rr * N + cc;
                    v0 += rp[0]; v1 += rp[1];
                }
                if (RND) { v0 = tf32r(v0); v1 = tf32r(v1); }
                if (TRNS) {
                    // C is V^T: [b][h][dh][S], cc and cc+1 share a head
                    size_t hb = ((size_t)(b * H_ + (cc >> 6)) * DH_ + (cc & 63))
                                * (size_t)M + rr;
                    C[hb] = v0;
                    C[hb + (size_t)M] = v1;
                } else {
                    *(float2*)&C[(size_t)b * M * N + (size_t)rr * N + cc] =
                        make_float2(v0, v1);
                }
            }
        }
    }
}

// ---------------------------------------------------------------------------
// Flash attention on mma.sync tf32.
// Block = 128 q-rows x (b,h); 8 warps, each 16 q-rows.
// S-tile: QK^T via mma (K tile K-major = B "col" layout directly).
// P -> smem (tf32-rounded) -> ldmatrix A-frags; V^T preloaded per-head.
// Padded 272B rows: 17x16B units -> conflict-free ldmatrix, no swizzle.
// ---------------------------------------------------------------------------
#define ATT_ROWB 272u
#define ATT_SMEM (128*272 + 64*272 + 64*272 + 128*272)

__global__ __launch_bounds__(256, 2) void attention_mma(
    const float* __restrict__ Q, const float* __restrict__ K,
    const float* __restrict__ VT, float* __restrict__ O)
{
    extern __shared__ __align__(16) char asmem[];
    uint32_t sm_q = smem_u32(asmem);
    uint32_t sm_k = sm_q + 128 * ATT_ROWB;
    uint32_t sm_v = sm_k + 64 * ATT_ROWB;
    uint32_t sm_p = sm_v + 64 * ATT_ROWB;

    int tid  = threadIdx.x;
    int wid  = tid >> 5;
    int lane = tid & 31;
    int q0   = blockIdx.x * 128;
    int h    = blockIdx.y;
    int b    = blockIdx.z;
    int lr   = lane & 15;
    int lh   = (lane >> 4) * 16;
    int qr   = lane >> 2;
    int qc   = (lane & 3) * 2;

    // Q tile load (128 rows x 64 floats)
    const float* Qg = Q + ((size_t)b * S_ + q0) * D_ + h * DH_;
    #pragma unroll
    for (int p = 0; p < 8; p++) {
        int idx = tid + p * 256;
        int r = idx >> 4, j = idx & 15;
        CP_ASYNC16(sm_q + (uint32_t)r * ATT_ROWB + j * 16,
                   Qg + (size_t)r * D_ + j * 4);
    }
    CP_ASYNC_COMMIT();

    float ofr[8][4];
    #pragma unroll
    for (int nf = 0; nf < 8; nf++)
        #pragma unroll
        for (int q = 0; q < 4; q++) ofr[nf][q] = 0.f;
    float m0 = -1e30f, m1 = -1e30f, l0 = 0.f, l1 = 0.f;

    const float* Kg = K  + (size_t)b * S_ * D_ + h * DH_;
    const float* Vg = VT + (size_t)(b * H_ + h) * DH_ * S_;

    uint32_t arow = sm_q + (uint32_t)(16 * wid + lr) * ATT_ROWB + lh;
    uint32_t prow = sm_p + (uint32_t)(16 * wid + lr) * ATT_ROWB + lh;
    uint32_t pst0 = sm_p + (uint32_t)(16 * wid + qr) * ATT_ROWB + qc * 4;
    uint32_t pst1 = pst0 + 8 * ATT_ROWB;

    for (int t = 0; t < S_ / 64; t++) {
        int k0 = t * 64;
        // K and V^T tiles (64 rows x 64 floats each)
        #pragma unroll
        for (int p = 0; p < 4; p++) {
            int idx = tid + p * 256;
            int r = idx >> 4, j = idx & 15;
            CP_ASYNC16(sm_k + (uint32_t)r * ATT_ROWB + j * 16,
                       Kg + (size_t)(k0 + r) * D_ + j * 4);
            CP_ASYNC16(sm_v + (uint32_t)r * ATT_ROWB + j * 16,
                       Vg + (size_t)r * S_ + k0 + j * 4);
        }
        CP_ASYNC_COMMIT();
        CP_ASYNC_WAIT0();
        __syncthreads();

        // S = Q K^T
        float sfr[8][4];
        #pragma unroll
        for (int nf = 0; nf < 8; nf++)
            #pragma unroll
            for (int q = 0; q < 4; q++) sfr[nf][q] = 0.f;

        #pragma unroll
        for (int ks = 0; ks < 8; ks++) {
            uint32_t afr[4], bfr[4][4];
            ldsm_x4(afr, arow + ks * 32);
            #pragma unroll
            for (int bf = 0; bf < 4; bf++)
                ldsm_x4(bfr[bf], sm_k + (uint32_t)(16 * bf + lr) * ATT_ROWB
                                   + ks * 32 + lh);
            #pragma unroll
            for (int nf = 0; nf < 8; nf++)
                mma_tf32(sfr[nf], afr,
                         bfr[nf >> 1][nf & 1], bfr[nf >> 1][2 + (nf & 1)]);
        }

        // scale + online softmax (two rows per thread: qr, qr+8)
        float mt0 = -1e30f, mt1 = -1e30f;
        #pragma unroll
        for (int nf = 0; nf < 8; nf++) {
            #pragma unroll
            for (int q = 0; q < 4; q++) sfr[nf][q] *= 0.125f;
            mt0 = fmaxf(mt0, fmaxf(sfr[nf][0], sfr[nf][1]));
            mt1 = fmaxf(mt1, fmaxf(sfr[nf][2], sfr[nf][3]));
        }
        mt0 = fmaxf(mt0, __shfl_xor_sync(0xffffffffu, mt0, 1));
        mt0 = fmaxf(mt0, __shfl_xor_sync(0xffffffffu, mt0, 2));
        mt1 = fmaxf(mt1, __shfl_xor_sync(0xffffffffu, mt1, 1));
        mt1 = fmaxf(mt1, __shfl_xor_sync(0xffffffffu, mt1, 2));
        float mn0 = fmaxf(m0, mt0), mn1 = fmaxf(m1, mt1);
        float c0 = __expf(m0 - mn0), c1 = __expf(m1 - mn1);
        float s0 = 0.f, s1 = 0.f;
        #pragma unroll
        for (int nf = 0; nf < 8; nf++) {
            float p0 = __expf(sfr[nf][0] - mn0);
            float p1 = __expf(sfr[nf][1] - mn0);
            float p2 = __expf(sfr[nf][2] - mn1);
            float p3 = __expf(sfr[nf][3] - mn1);
            s0 += p0 + p1; s1 += p2 + p3;
            asm volatile("st.shared.v2.f32 [%0], {%1,%2};"
                         :: "r"(pst0 + nf * 32), "f"(tf32r(p0)), "f"(tf32r(p1)));
            asm volatile("st.shared.v2.f32 [%0], {%1,%2};"
                         :: "r"(pst1 + nf * 32), "f"(tf32r(p2)), "f"(tf32r(p3)));
        }
        s0 += __shfl_xor_sync(0xffffffffu, s0, 1);
        s0 += __shfl_xor_sync(0xffffffffu, s0, 2);
        s1 += __shfl_xor_sync(0xffffffffu, s1, 1);
        s1 += __shfl_xor_sync(0xffffffffu, s1, 2);
        l0 = l0 * c0 + s0;  l1 = l1 * c1 + s1;
        m0 = mn0;  m1 = mn1;
        #pragma unroll
        for (int nf = 0; nf < 8; nf++) {
            ofr[nf][0] *= c0; ofr[nf][1] *= c0;
            ofr[nf][2] *= c1; ofr[nf][3] *= c1;
        }
        __syncwarp();

        // O += P V   (A = P rows of this warp, B = V^T rows = head dims)
        #pragma unroll
        for (int ks = 0; ks < 8; ks++) {
            uint32_t afr[4], bfr[4][4];
            ldsm_x4(afr, prow + ks * 32);
            #pragma unroll
            for (int bf = 0; bf < 4; bf++)
                ldsm_x4(bfr[bf], sm_v + (uint32_t)(16 * bf + lr) * ATT_ROWB
                                   + ks * 32 + lh);
            #pragma unroll
            for (int nf = 0; nf < 8; nf++)
                mma_tf32(ofr[nf], afr,
                         bfr[nf >> 1][nf & 1], bfr[nf >> 1][2 + (nf & 1)]);
        }
        __syncthreads();
    }

    // Normalize + store (tf32-rounded: feeds Wo GEMM)
    float i0 = 1.f / l0, i1 = 1.f / l1;
    float* Og = O + ((size_t)b * S_ + q0) * D_ + h * DH_;
    int r0 = 16 * wid + qr;
    #pragma unroll
    for (int nf = 0; nf < 8; nf++) {
        int cc = 8 * nf + qc;
        *(float2*)&Og[(size_t)r0 * D_ + cc] =
            make_float2(tf32r(ofr[nf][0] * i0), tf32r(ofr[nf][1] * i0));
        *(float2*)&Og[(size_t)(r0 + 8) * D_ + cc] =
            make_float2(tf32r(ofr[nf][2] * i1), tf32r(ofr[nf][3] * i1));
    }
}

// ---------------------------------------------------------------------------
// Launch
// ---------------------------------------------------------------------------
extern "C" void kernel_launch(void* const* d_in, const int* in_sizes, int n_in,
                              void* d_out, int out_size)
{
    (void)in_sizes; (void)n_in; (void)out_size;
    const float* x    = (const float*)d_in[0];
    const int*   lidx = (const int*)  d_in[1];
    const float* Wq = (const float*)d_in[2];  const float* bq = (const float*)d_in[3];
    const float* Wk = (const float*)d_in[4];  const float* bk = (const float*)d_in[5];
    const float* Wv = (const float*)d_in[6];  const float* bv = (const float*)d_in[7];
    const float* Wo = (const float*)d_in[8];  const float* bo = (const float*)d_in[9];
    const float* s1 = (const float*)d_in[10]; const float* b1n = (const float*)d_in[11];
    const float* s2 = (const float*)d_in[12]; const float* b2n = (const float*)d_in[13];
    const float* W1 = (const float*)d_in[14]; const float* bf1 = (const float*)d_in[15];
    const float* W2 = (const float*)d_in[16]; const float* bf2 = (const float*)d_in[17];
    float* out = (float*)d_out;

    float *h_, *q_, *k_, *vT_, *at_, *ff_;
    float *wqT, *wkT, *wvT, *woT, *w1T, *w2T;
    cudaGetSymbolAddress((void**)&h_,  g_h);
    cudaGetSymbolAddress((void**)&q_,  g_q);
    cudaGetSymbolAddress((void**)&k_,  g_k);
    cudaGetSymbolAddress((void**)&vT_, g_vT);
    cudaGetSymbolAddress((void**)&at_, g_attn);
    cudaGetSymbolAddress((void**)&ff_, g_ffn);
    cudaGetSymbolAddress((void**)&wqT, g_WqT);
    cudaGetSymbolAddress((void**)&wkT, g_WkT);
    cudaGetSymbolAddress((void**)&wvT, g_WvT);
    cudaGetSymbolAddress((void**)&woT, g_WoT);
    cudaGetSymbolAddress((void**)&w1T, g_W1T);
    cudaGetSymbolAddress((void**)&w2T, g_W2T);

    cudaFuncSetAttribute(attention_mma,
                         cudaFuncAttributeMaxDynamicSharedMemorySize, ATT_SMEM);
    cudaFuncSetAttribute(gemm_mma<0,0,1,0>,
                         cudaFuncAttributeMaxDynamicSharedMemorySize, GEMM_SMEM);
    cudaFuncSetAttribute(gemm_mma<0,0,1,1>,
                         cudaFuncAttributeMaxDynamicSharedMemorySize, GEMM_SMEM);
    cudaFuncSetAttribute(gemm_mma<0,1,0,0>,
                         cudaFuncAttributeMaxDynamicSharedMemorySize, GEMM_SMEM);
    cudaFuncSetAttribute(gemm_mma<1,0,1,0>,
                         cudaFuncAttributeMaxDynamicSharedMemorySize, GEMM_SMEM);

    // Weight transpose + tf32 rounding
    dim3 tb(32, 8);
    transpose_round_kernel<<<dim3(D_/32, D_/32, L_), tb>>>(Wq, wqT, D_, D_);
    transpose_round_kernel<<<dim3(D_/32, D_/32, L_), tb>>>(Wk, wkT, D_, D_);
    transpose_round_kernel<<<dim3(D_/32, D_/32, L_), tb>>>(Wv, wvT, D_, D_);
    transpose_round_kernel<<<dim3(D_/32, D_/32, L_), tb>>>(Wo, woT, D_, D_);
    transpose_round_kernel<<<dim3(F_/32, D_/32, L_), tb>>>(W1, w1T, D_, F_);
    transpose_round_kernel<<<dim3(D_/32, F_/32, L_), tb>>>(W2, w2T, F_, D_);

    dim3 gD(D_ / 128, S_ / 128, B_);
    dim3 gF(F_ / 128, S_ / 128, B_);

    // LN1 -> h (tf32-rounded)
    ln_kernel<<<B_ * S_, 256>>>(x, s1, b1n, lidx, h_);
    // QKV (tf32-rounded: feed tensor-core attention); V written transposed
    gemm_mma<0,0,1,0><<<gD, 256, GEMM_SMEM>>>(h_, wqT, bq, lidx, nullptr, q_,  S_, D_, D_);
    gemm_mma<0,0,1,0><<<gD, 256, GEMM_SMEM>>>(h_, wkT, bk, lidx, nullptr, k_,  S_, D_, D_);
    gemm_mma<0,0,1,1><<<gD, 256, GEMM_SMEM>>>(h_, wvT, bv, lidx, nullptr, vT_, S_, D_, D_);
    // Attention (tensor-core)
    attention_mma<<<dim3(S_ / 128, H_, B_), 256, ATT_SMEM>>>(q_, k_, vT_, at_);
    // O-proj + residual(x) -> out
    gemm_mma<0,1,0,0><<<gD, 256, GEMM_SMEM>>>(at_, woT, bo, lidx, x, out, S_, D_, D_);
    // LN2 -> h (tf32-rounded)
    ln_kernel<<<B_ * S_, 256>>>(out, s2, b2n, lidx, h_);
    // FFN1 + GELU (tf32-rounded -> FFN2 input)
    gemm_mma<1,0,1,0><<<gF, 256, GEMM_SMEM>>>(h_, w1T, bf1, lidx, nullptr, ff_, S_, D_, F_);
    // FFN2 + residual(out) -> final
    gemm_mma<0,1,0,0><<<gD, 256, GEMM_SMEM>>>(ff_, w2T, bf2, lidx, out, out, S_, F_, D_);
}

// round 8
// speedup vs baseline: 1.7684x; 1.0222x over previous
#include <cuda_runtime.h>
#include <math.h>
#include <stdint.h>

// Problem dims
#define L_  8
#define B_  8
#define S_  2048
#define D_  1024
#define H_  16
#define DH_ 64
#define F_  4096

// ---------------------------------------------------------------------------
// Scratch (__device__ globals; allocation-guard-safe)
// ---------------------------------------------------------------------------
__device__ float g_h   [(size_t)B_ * S_ * D_];
__device__ float g_q   [(size_t)B_ * S_ * D_];
__device__ float g_k   [(size_t)B_ * S_ * D_];
__device__ float g_vT  [(size_t)B_ * H_ * DH_ * S_];   // V transposed per head
__device__ float g_attn[(size_t)B_ * S_ * D_];
__device__ float g_ffn [(size_t)B_ * S_ * F_];
// Transposed + tf32-rounded weights: Wt[l][n][k]
__device__ float g_WqT[(size_t)L_ * D_ * D_];
__device__ float g_WkT[(size_t)L_ * D_ * D_];
__device__ float g_WvT[(size_t)L_ * D_ * D_];
__device__ float g_WoT[(size_t)L_ * D_ * D_];
__device__ float g_W1T[(size_t)L_ * D_ * F_];
__device__ float g_W2T[(size_t)L_ * F_ * D_];

// ---------------------------------------------------------------------------
// Helpers (baseline PTX only — no 'a'-suffix accel features)
// ---------------------------------------------------------------------------
__device__ __forceinline__ uint32_t smem_u32(const void* p) {
    uint32_t a;
    asm("{ .reg .u64 t; cvta.to.shared.u64 t, %1; cvt.u32.u64 %0, t; }"
        : "=r"(a) : "l"(p));
    return a;
}

__device__ __forceinline__ float tf32r(float x) {   // round-to-nearest tf32
    uint32_t u;
    asm("cvt.rna.tf32.f32 %0, %1;" : "=r"(u) : "f"(x));
    return __uint_as_float(u);
}

#define SMEM_SWZ128(o) ((o) ^ (((o) >> 3) & 0x70))

#define CP_ASYNC16(dst_u32, src_ptr) \
    asm volatile("cp.async.cg.shared.global [%0], [%1], 16;" \
                 :: "r"(dst_u32), "l"(src_ptr))
#define CP_ASYNC_COMMIT() asm volatile("cp.async.commit_group;" ::: "memory")
#define CP_ASYNC_WAIT1()  asm volatile("cp.async.wait_group 1;" ::: "memory")
#define CP_ASYNC_WAIT0()  asm volatile("cp.async.wait_group 0;" ::: "memory")

__device__ __forceinline__ void ldsm_x4(uint32_t (&r)[4], uint32_t addr) {
    asm volatile("ldmatrix.sync.aligned.m8n8.x4.shared.b16 {%0,%1,%2,%3}, [%4];"
                 : "=r"(r[0]), "=r"(r[1]), "=r"(r[2]), "=r"(r[3]) : "r"(addr));
}

__device__ __forceinline__ void mma_tf32(float (&d)[4],
                                         const uint32_t (&a)[4],
                                         uint32_t b0, uint32_t b1) {
    asm volatile(
        "mma.sync.aligned.m16n8k8.row.col.f32.tf32.tf32.f32 "
        "{%0,%1,%2,%3}, {%4,%5,%6,%7}, {%8,%9}, {%0,%1,%2,%3};"
        : "+f"(d[0]), "+f"(d[1]), "+f"(d[2]), "+f"(d[3])
        : "r"(a[0]), "r"(a[1]), "r"(a[2]), "r"(a[3]), "r"(b0), "r"(b1));
}

// ---------------------------------------------------------------------------
// GELU (tanh approx — matches jax.nn.gelu default)
// ---------------------------------------------------------------------------
__device__ __forceinline__ float gelu_f(float x)
{
    float t = 0.7978845608028654f * (x + 0.044715f * x * x * x);
    float th;
    asm("tanh.approx.f32 %0, %1;" : "=f"(th) : "f"(t));
    return 0.5f * x * (1.0f + th);
}

// ---------------------------------------------------------------------------
// Weight transpose + tf32 RN round: W[l][K][N] -> Wt[l][N][K]
// ---------------------------------------------------------------------------
__global__ __launch_bounds__(256) void transpose_round_kernel(
    const float* __restrict__ W, float* __restrict__ Wt, int Kd, int Nd)
{
    __shared__ float t[32][33];
    int l  = blockIdx.z;
    int n0 = blockIdx.x * 32;
    int k0 = blockIdx.y * 32;
    const float* Wl  = W  + (size_t)l * Kd * Nd;
    float*       Wtl = Wt + (size_t)l * Nd * Kd;
    int c = threadIdx.x, r0 = threadIdx.y;
    #pragma unroll
    for (int i = 0; i < 4; i++) {
        int r = r0 + i * 8;
        t[r][c] = Wl[(size_t)(k0 + r) * Nd + n0 + c];
    }
    __syncthreads();
    #pragma unroll
    for (int i = 0; i < 4; i++) {
        int r = r0 + i * 8;
        Wtl[(size_t)(n0 + r) * Kd + k0 + c] = tf32r(t[c][r]);
    }
}

// ---------------------------------------------------------------------------
// LayerNorm (rounds output to tf32 — feeds tensor-core GEMMs)
// ---------------------------------------------------------------------------
__global__ __launch_bounds__(256) void ln_kernel(
    const float* __restrict__ X,
    const float* __restrict__ sall, const float* __restrict__ ball,
    const int* __restrict__ lidx, float* __restrict__ Y)
{
    int row = blockIdx.x;
    int b   = row / S_;
    int tid = threadIdx.x;

    float4 xv = ((const float4*)(X + (size_t)row * D_))[tid];
    float s  = xv.x + xv.y + xv.z + xv.w;
    float ss = xv.x*xv.x + xv.y*xv.y + xv.z*xv.z + xv.w*xv.w;
    #pragma unroll
    for (int o = 16; o > 0; o >>= 1) {
        s  += __shfl_xor_sync(0xffffffffu, s,  o);
        ss += __shfl_xor_sync(0xffffffffu, ss, o);
    }
    __shared__ float rs[8], rss[8], mv[2];
    int wid = tid >> 5, lane = tid & 31;
    if (lane == 0) { rs[wid] = s; rss[wid] = ss; }
    __syncthreads();
    if (tid == 0) {
        float a = 0.f, c = 0.f;
        #pragma unroll
        for (int w = 0; w < 8; w++) { a += rs[w]; c += rss[w]; }
        float mean = a * (1.0f / D_);
        float var  = c * (1.0f / D_) - mean * mean;
        mv[0] = mean; mv[1] = rsqrtf(var + 1e-5f);
    }
    __syncthreads();
    float mean = mv[0], rstd = mv[1];

    int li = lidx[b];
    float4 sv = ((const float4*)(sall + (size_t)li * D_))[tid];
    float4 bv = ((const float4*)(ball + (size_t)li * D_))[tid];
    float4 o;
    o.x = tf32r((xv.x - mean) * rstd * sv.x + bv.x);
    o.y = tf32r((xv.y - mean) * rstd * sv.y + bv.y);
    o.z = tf32r((xv.z - mean) * rstd * sv.z + bv.z);
    o.w = tf32r((xv.w - mean) * rstd * sv.w + bv.w);
    ((float4*)(Y + (size_t)row * D_))[tid] = o;
}

// ---------------------------------------------------------------------------
// Shared GEMM mainloop: 128x128 tile, BK=32, 8 warps (2x4), warp 64x32.
// 3-stage cp.async ring, SW128 swizzle, ldmatrix fragments, m16n8k8 tf32.
// ---------------------------------------------------------------------------
#define GEMM_SMEM (1024 + 3 * 32768)

struct MainloopOut { float acc[4][4][4]; };

__device__ __forceinline__ void gemm_mainloop(
    const float* __restrict__ Ag, const float* __restrict__ Bg,
    int K, uint32_t sbase, int tid, int wm, int wn, int lane,
    float (&acc)[4][4][4])
{
    #pragma unroll
    for (int i = 0; i < 4; i++)
        #pragma unroll
        for (int j = 0; j < 4; j++)
            #pragma unroll
            for (int q = 0; q < 4; q++) acc[i][j][q] = 0.f;

    auto load_stage = [&](int kc, int stg) {
        uint32_t sA = sbase + (uint32_t)stg * 32768u;
        uint32_t sB = sA + 16384u;
        const float* Ak = Ag + kc * 32;
        const float* Bk = Bg + kc * 32;
        #pragma unroll
        for (int p = 0; p < 4; p++) {
            int idx = tid + p * 256;
            int r  = idx >> 3;
            int kb = (idx & 7) * 16;
            uint32_t sw = SMEM_SWZ128((uint32_t)(r * 128 + kb));
            CP_ASYNC16(sA + sw, Ak + (size_t)r * K + (kb >> 2));
            CP_ASYNC16(sB + sw, Bk + (size_t)r * K + (kb >> 2));
        }
        CP_ASYNC_COMMIT();
    };

    int nk = K >> 5;
    load_stage(0, 0);
    load_stage(1, 1);

    int lr = lane & 15;
    int lh = (lane >> 4) * 16;

    for (int i = 0; i < nk; i++) {
        if (i < nk - 2) CP_ASYNC_WAIT1(); else CP_ASYNC_WAIT0();
        __syncthreads();
        if (i + 2 < nk) load_stage(i + 2, (i + 2) % 3);

        uint32_t sA = sbase + (uint32_t)(i % 3) * 32768u;
        uint32_t sB = sA + 16384u;

        #pragma unroll
        for (int ks = 0; ks < 4; ks++) {
            uint32_t afr[4][4];
            uint32_t bfr[2][4];
            #pragma unroll
            for (int mf = 0; mf < 4; mf++) {
                uint32_t off = (uint32_t)((64 * wm + 16 * mf + lr) * 128
                                          + ks * 32 + lh);
                ldsm_x4(afr[mf], sA + SMEM_SWZ128(off));
            }
            #pragma unroll
            for (int bf = 0; bf < 2; bf++) {
                uint32_t off = (uint32_t)((32 * wn + 16 * bf + lr) * 128
                                          + ks * 32 + lh);
                ldsm_x4(bfr[bf], sB + SMEM_SWZ128(off));
            }
            #pragma unroll
            for (int mf = 0; mf < 4; mf++)
                #pragma unroll
                for (int nf = 0; nf < 4; nf++)
                    mma_tf32(acc[mf][nf], afr[mf],
                             bfr[nf >> 1][nf & 1], bfr[nf >> 1][2 + (nf & 1)]);
        }
    }
}

// ---------------------------------------------------------------------------
// Generic GEMM: C[b] = A[b](MxK) @ Wt[lidx[b]](NxK)^T + bias
//   (+GELU) (+residual) (+tf32 round on store)
// ---------------------------------------------------------------------------
template <int ACT, int RES, int RND>
__global__ __launch_bounds__(256, 2)
void gemm_mma(const float* __restrict__ A, const float* __restrict__ WT,
              const float* __restrict__ biasall, const int* __restrict__ lidx,
              const float* __restrict__ Res, float* __restrict__ C,
              int M, int K, int N)
{
    extern __shared__ __align__(16) char smraw[];
    uint32_t sbase = (smem_u32(smraw) + 1023u) & ~1023u;

    int tid  = threadIdx.x;
    int wid  = tid >> 5;
    int lane = tid & 31;
    int wm   = wid >> 2;
    int wn   = wid & 3;
    int b    = blockIdx.z;
    int li   = lidx[b];
    int row0 = blockIdx.y * 128;
    int col0 = blockIdx.x * 128;

    const float* Ag = A  + (size_t)b  * M * K + (size_t)row0 * K;
    const float* Bg = WT + (size_t)li * N * K + (size_t)col0 * K;

    float acc[4][4][4];
    gemm_mainloop(Ag, Bg, K, sbase, tid, wm, wn, lane, acc);

    int qr = lane >> 2;
    int qc = (lane & 3) * 2;
    const float* bp = biasall + (size_t)li * N;
    #pragma unroll
    for (int mf = 0; mf < 4; mf++) {
        int r = row0 + 64 * wm + 16 * mf + qr;
        #pragma unroll
        for (int nf = 0; nf < 4; nf++) {
            int cc = col0 + 32 * wn + 8 * nf + qc;
            #pragma unroll
            for (int half = 0; half < 2; half++) {
                int rr = r + half * 8;
                float v0 = acc[mf][nf][half * 2 + 0] + bp[cc + 0];
                float v1 = acc[mf][nf][half * 2 + 1] + bp[cc + 1];
                if (ACT) { v0 = gelu_f(v0); v1 = gelu_f(v1); }
                if (RES) {
                    float2 rv = *(const float2*)&Res[(size_t)b * M * N
                                                     + (size_t)rr * N + cc];
                    v0 += rv.x; v1 += rv.y;
                }
                if (RND) { v0 = tf32r(v0); v1 = tf32r(v1); }
                *(float2*)&C[(size_t)b * M * N + (size_t)rr * N + cc] =
                    make_float2(v0, v1);
            }
        }
    }
}

// ---------------------------------------------------------------------------
// Fused QKV GEMM: one launch, grid.x = 24 (matrix = x/8, col-block = x%8).
// Q,K outputs row-major tf32-rounded; V output transposed per head.
// ---------------------------------------------------------------------------
__global__ __launch_bounds__(256, 2)
void gemm_qkv(const float* __restrict__ A,
              const float* __restrict__ WqT, const float* __restrict__ WkT,
              const float* __restrict__ WvT,
              const float* __restrict__ bqa, const float* __restrict__ bka,
              const float* __restrict__ bva,
              const int* __restrict__ lidx,
              float* __restrict__ Oq, float* __restrict__ Ok,
              float* __restrict__ OvT)
{
    extern __shared__ __align__(16) char smraw[];
    uint32_t sbase = (smem_u32(smraw) + 1023u) & ~1023u;

    const int M = S_, K = D_, N = D_;
    int tid  = threadIdx.x;
    int wid  = tid >> 5;
    int lane = tid & 31;
    int wm   = wid >> 2;
    int wn   = wid & 3;
    int b    = blockIdx.z;
    int li   = lidx[b];
    int row0 = blockIdx.y * 128;
    int mat  = blockIdx.x >> 3;         // 0=q 1=k 2=v
    int col0 = (blockIdx.x & 7) * 128;

    const float* WT = (mat == 0) ? WqT : (mat == 1) ? WkT : WvT;
    const float* ba = (mat == 0) ? bqa : (mat == 1) ? bka : bva;

    const float* Ag = A  + (size_t)b  * M * K + (size_t)row0 * K;
    const float* Bg = WT + (size_t)li * N * K + (size_t)col0 * K;

    float acc[4][4][4];
    gemm_mainloop(Ag, Bg, K, sbase, tid, wm, wn, lane, acc);

    int qr = lane >> 2;
    int qc = (lane & 3) * 2;
    const float* bp = ba + (size_t)li * N;

    if (mat < 2) {
        float* C = (mat == 0) ? Oq : Ok;
        #pragma unroll
        for (int mf = 0; mf < 4; mf++) {
            int r = row0 + 64 * wm + 16 * mf + qr;
            #pragma unroll
            for (int nf = 0; nf < 4; nf++) {
                int cc = col0 + 32 * wn + 8 * nf + qc;
                #pragma unroll
                for (int half = 0; half < 2; half++) {
                    int rr = r + half * 8;
                    float v0 = tf32r(acc[mf][nf][half * 2 + 0] + bp[cc + 0]);
                    float v1 = tf32r(acc[mf][nf][half * 2 + 1] + bp[cc + 1]);
                    *(float2*)&C[(size_t)b * M * N + (size_t)rr * N + cc] =
                        make_float2(v0, v1);
                }
            }
        }
    } else {
        #pragma unroll
        for (int mf = 0; mf < 4; mf++) {
            int r = row0 + 64 * wm + 16 * mf + qr;
            #pragma unroll
            for (int nf = 0; nf < 4; nf++) {
                int cc = col0 + 32 * wn + 8 * nf + qc;
                #pragma unroll
                for (int half = 0; half < 2; half++) {
                    int rr = r + half * 8;
                    float v0 = tf32r(acc[mf][nf][half * 2 + 0] + bp[cc + 0]);
                    float v1 = tf32r(acc[mf][nf][half * 2 + 1] + bp[cc + 1]);
                    size_t hb = ((size_t)(b * H_ + (cc >> 6)) * DH_ + (cc & 63))
                                * (size_t)M + rr;
                    OvT[hb] = v0;
                    OvT[hb + (size_t)M] = v1;
                }
            }
        }
    }
}

// ---------------------------------------------------------------------------
// Flash attention on mma.sync tf32 — split K/V commit groups so the V load
// overlaps QK^T + softmax. Padded 272B rows (conflict-free ldmatrix).
// ---------------------------------------------------------------------------
#define ATT_ROWB 272u
#define ATT_SMEM (128*272 + 64*272 + 64*272 + 128*272)

__global__ __launch_bounds__(256, 2) void attention_mma(
    const float* __restrict__ Q, const float* __restrict__ K,
    const float* __restrict__ VT, float* __restrict__ O)
{
    extern __shared__ __align__(16) char asmem[];
    uint32_t sm_q = smem_u32(asmem);
    uint32_t sm_k = sm_q + 128 * ATT_ROWB;
    uint32_t sm_v = sm_k + 64 * ATT_ROWB;
    uint32_t sm_p = sm_v + 64 * ATT_ROWB;

    int tid  = threadIdx.x;
    int wid  = tid >> 5;
    int lane = tid & 31;
    int q0   = blockIdx.x * 128;
    int h    = blockIdx.y;
    int b    = blockIdx.z;
    int lr   = lane & 15;
    int lh   = (lane >> 4) * 16;
    int qr   = lane >> 2;
    int qc   = (lane & 3) * 2;

    // Q tile load (group 0)
    const float* Qg = Q + ((size_t)b * S_ + q0) * D_ + h * DH_;
    #pragma unroll
    for (int p = 0; p < 8; p++) {
        int idx = tid + p * 256;
        int r = idx >> 4, j = idx & 15;
        CP_ASYNC16(sm_q + (uint32_t)r * ATT_ROWB + j * 16,
                   Qg + (size_t)r * D_ + j * 4);
    }
    CP_ASYNC_COMMIT();

    float ofr[8][4];
    #pragma unroll
    for (int nf = 0; nf < 8; nf++)
        #pragma unroll
        for (int q = 0; q < 4; q++) ofr[nf][q] = 0.f;
    float m0 = -1e30f, m1 = -1e30f, l0 = 0.f, l1 = 0.f;

    const float* Kg = K  + (size_t)b * S_ * D_ + h * DH_;
    const float* Vg = VT + (size_t)(b * H_ + h) * DH_ * S_;

    uint32_t arow = sm_q + (uint32_t)(16 * wid + lr) * ATT_ROWB + lh;
    uint32_t prow = sm_p + (uint32_t)(16 * wid + lr) * ATT_ROWB + lh;
    uint32_t pst0 = sm_p + (uint32_t)(16 * wid + qr) * ATT_ROWB + qc * 4;
    uint32_t pst1 = pst0 + 8 * ATT_ROWB;

    for (int t = 0; t < S_ / 64; t++) {
        int k0 = t * 64;
        // K tile (own commit group)
        #pragma unroll
        for (int p = 0; p < 4; p++) {
            int idx = tid + p * 256;
            int r = idx >> 4, j = idx & 15;
            CP_ASYNC16(sm_k + (uint32_t)r * ATT_ROWB + j * 16,
                       Kg + (size_t)(k0 + r) * D_ + j * 4);
        }
        CP_ASYNC_COMMIT();
        // V tile (separate group — stays in flight through QK^T)
        #pragma unroll
        for (int p = 0; p < 4; p++) {
            int idx = tid + p * 256;
            int r = idx >> 4, j = idx & 15;
            CP_ASYNC16(sm_v + (uint32_t)r * ATT_ROWB + j * 16,
                       Vg + (size_t)r * S_ + k0 + j * 4);
        }
        CP_ASYNC_COMMIT();
        CP_ASYNC_WAIT1();     // Q (t==0) and K complete; V outstanding
        __syncthreads();

        // S = Q K^T
        float sfr[8][4];
        #pragma unroll
        for (int nf = 0; nf < 8; nf++)
            #pragma unroll
            for (int q = 0; q < 4; q++) sfr[nf][q] = 0.f;

        #pragma unroll
        for (int ks = 0; ks < 8; ks++) {
            uint32_t afr[4], bfr[4][4];
            ldsm_x4(afr, arow + ks * 32);
            #pragma unroll
            for (int bf = 0; bf < 4; bf++)
                ldsm_x4(bfr[bf], sm_k + (uint32_t)(16 * bf + lr) * ATT_ROWB
                                   + ks * 32 + lh);
            #pragma unroll
            for (int nf = 0; nf < 8; nf++)
                mma_tf32(sfr[nf], afr,
                         bfr[nf >> 1][nf & 1], bfr[nf >> 1][2 + (nf & 1)]);
        }

        // scale + online softmax (rows qr, qr+8 per thread)
        float mt0 = -1e30f, mt1 = -1e30f;
        #pragma unroll
        for (int nf = 0; nf < 8; nf++) {
            #pragma unroll
            for (int q = 0; q < 4; q++) sfr[nf][q] *= 0.125f;
            mt0 = fmaxf(mt0, fmaxf(sfr[nf][0], sfr[nf][1]));
            mt1 = fmaxf(mt1, fmaxf(sfr[nf][2], sfr[nf][3]));
        }
        mt0 = fmaxf(mt0, __shfl_xor_sync(0xffffffffu, mt0, 1));
        mt0 = fmaxf(mt0, __shfl_xor_sync(0xffffffffu, mt0, 2));
        mt1 = fmaxf(mt1, __shfl_xor_sync(0xffffffffu, mt1, 1));
        mt1 = fmaxf(mt1, __shfl_xor_sync(0xffffffffu, mt1, 2));
        float mn0 = fmaxf(m0, mt0), mn1 = fmaxf(m1, mt1);
        float c0 = __expf(m0 - mn0), c1 = __expf(m1 - mn1);
        float s0 = 0.f, s1 = 0.f;
        #pragma unroll
        for (int nf = 0; nf < 8; nf++) {
            float p0 = __expf(sfr[nf][0] - mn0);
            float p1 = __expf(sfr[nf][1] - mn0);
            float p2 = __expf(sfr[nf][2] - mn1);
            float p3 = __expf(sfr[nf][3] - mn1);
            s0 += p0 + p1; s1 += p2 + p3;
            asm volatile("st.shared.v2.f32 [%0], {%1,%2};"
                         :: "r"(pst0 + nf * 32), "f"(tf32r(p0)), "f"(tf32r(p1)));
            asm volatile("st.shared.v2.f32 [%0], {%1,%2};"
                         :: "r"(pst1 + nf * 32), "f"(tf32r(p2)), "f"(tf32r(p3)));
        }
        s0 += __shfl_xor_sync(0xffffffffu, s0, 1);
        s0 += __shfl_xor_sync(0xffffffffu, s0, 2);
        s1 += __shfl_xor_sync(0xffffffffu, s1, 1);
        s1 += __shfl_xor_sync(0xffffffffu, s1, 2);
        l0 = l0 * c0 + s0;  l1 = l1 * c1 + s1;
        m0 = mn0;  m1 = mn1;
        #pragma unroll
        for (int nf = 0; nf < 8; nf++) {
            ofr[nf][0] *= c0; ofr[nf][1] *= c0;
            ofr[nf][2] *= c1; ofr[nf][3] *= c1;
        }
        __syncwarp();

        CP_ASYNC_WAIT0();     // V arrived
        __syncthreads();

        // O += P V   (A = this warp's P rows, B = V^T rows = head dims)
        #pragma unroll
        for (int ks = 0; ks < 8; ks++) {
            uint32_t afr[4], bfr[4][4];
            ldsm_x4(afr, prow + ks * 32);
            #pragma unroll
            for (int bf = 0; bf < 4; bf++)
                ldsm_x4(bfr[bf], sm_v + (uint32_t)(16 * bf + lr) * ATT_ROWB
                                   + ks * 32 + lh);
            #pragma unroll
            for (int nf = 0; nf < 8; nf++)
                mma_tf32(ofr[nf], afr,
                         bfr[nf >> 1][nf & 1], bfr[nf >> 1][2 + (nf & 1)]);
        }
        __syncthreads();
    }

    // Normalize + store (tf32-rounded: feeds Wo GEMM)
    float i0 = 1.f / l0, i1 = 1.f / l1;
    float* Og = O + ((size_t)b * S_ + q0) * D_ + h * DH_;
    int r0 = 16 * wid + qr;
    #pragma unroll
    for (int nf = 0; nf < 8; nf++) {
        int cc = 8 * nf + qc;
        *(float2*)&Og[(size_t)r0 * D_ + cc] =
            make_float2(tf32r(ofr[nf][0] * i0), tf32r(ofr[nf][1] * i0));
        *(float2*)&Og[(size_t)(r0 + 8) * D_ + cc] =
            make_float2(tf32r(ofr[nf][2] * i1), tf32r(ofr[nf][3] * i1));
    }
}

// ---------------------------------------------------------------------------
// Launch
// ---------------------------------------------------------------------------
extern "C" void kernel_launch(void* const* d_in, const int* in_sizes, int n_in,
                              void* d_out, int out_size)
{
    (void)in_sizes; (void)n_in; (void)out_size;
    const float* x    = (const float*)d_in[0];
    const int*   lidx = (const int*)  d_in[1];
    const float* Wq = (const float*)d_in[2];  const float* bq = (const float*)d_in[3];
    const float* Wk = (const float*)d_in[4];  const float* bk = (const float*)d_in[5];
    const float* Wv = (const float*)d_in[6];  const float* bv = (const float*)d_in[7];
    const float* Wo = (const float*)d_in[8];  const float* bo = (const float*)d_in[9];
    const float* s1 = (const float*)d_in[10]; const float* b1n = (const float*)d_in[11];
    const float* s2 = (const float*)d_in[12]; const float* b2n = (const float*)d_in[13];
    const float* W1 = (const float*)d_in[14]; const float* bf1 = (const float*)d_in[15];
    const float* W2 = (const float*)d_in[16]; const float* bf2 = (const float*)d_in[17];
    float* out = (float*)d_out;

    float *h_, *q_, *k_, *vT_, *at_, *ff_;
    float *wqT, *wkT, *wvT, *woT, *w1T, *w2T;
    cudaGetSymbolAddress((void**)&h_,  g_h);
    cudaGetSymbolAddress((void**)&q_,  g_q);
    cudaGetSymbolAddress((void**)&k_,  g_k);
    cudaGetSymbolAddress((void**)&vT_, g_vT);
    cudaGetSymbolAddress((void**)&at_, g_attn);
    cudaGetSymbolAddress((void**)&ff_, g_ffn);
    cudaGetSymbolAddress((void**)&wqT, g_WqT);
    cudaGetSymbolAddress((void**)&wkT, g_WkT);
    cudaGetSymbolAddress((void**)&wvT, g_WvT);
    cudaGetSymbolAddress((void**)&woT, g_WoT);
    cudaGetSymbolAddress((void**)&w1T, g_W1T);
    cudaGetSymbolAddress((void**)&w2T, g_W2T);

    cudaFuncSetAttribute(attention_mma,
                         cudaFuncAttributeMaxDynamicSharedMemorySize, ATT_SMEM);
    cudaFuncSetAttribute(gemm_qkv,
                         cudaFuncAttributeMaxDynamicSharedMemorySize, GEMM_SMEM);
    cudaFuncSetAttribute(gemm_mma<0,1,0>,
                         cudaFuncAttributeMaxDynamicSharedMemorySize, GEMM_SMEM);
    cudaFuncSetAttribute(gemm_mma<1,0,1>,
                         cudaFuncAttributeMaxDynamicSharedMemorySize, GEMM_SMEM);

    // Weight transpose + tf32 rounding
    dim3 tb(32, 8);
    transpose_round_kernel<<<dim3(D_/32, D_/32, L_), tb>>>(Wq, wqT, D_, D_);
    transpose_round_kernel<<<dim3(D_/32, D_/32, L_), tb>>>(Wk, wkT, D_, D_);
    transpose_round_kernel<<<dim3(D_/32, D_/32, L_), tb>>>(Wv, wvT, D_, D_);
    transpose_round_kernel<<<dim3(D_/32, D_/32, L_), tb>>>(Wo, woT, D_, D_);
    transpose_round_kernel<<<dim3(F_/32, D_/32, L_), tb>>>(W1, w1T, D_, F_);
    transpose_round_kernel<<<dim3(D_/32, F_/32, L_), tb>>>(W2, w2T, F_, D_);

    dim3 gD(D_ / 128, S_ / 128, B_);
    dim3 gF(F_ / 128, S_ / 128, B_);

    // LN1 -> h (tf32-rounded)
    ln_kernel<<<B_ * S_, 256>>>(x, s1, b1n, lidx, h_);
    // Fused QKV (one launch, 3072 CTAs); V written transposed
    gemm_qkv<<<dim3(24, S_ / 128, B_), 256, GEMM_SMEM>>>(
        h_, wqT, wkT, wvT, bq, bk, bv, lidx, q_, k_, vT_);
    // Attention (tensor-core, split K/V wait)
    attention_mma<<<dim3(S_ / 128, H_, B_), 256, ATT_SMEM>>>(q_, k_, vT_, at_);
    // O-proj + residual(x) -> out
    gemm_mma<0,1,0><<<gD, 256, GEMM_SMEM>>>(at_, woT, bo, lidx, x, out, S_, D_, D_);
    // LN2 -> h (tf32-rounded)
    ln_kernel<<<B_ * S_, 256>>>(out, s2, b2n, lidx, h_);
    // FFN1 + GELU (tf32-rounded -> FFN2 input)
    gemm_mma<1,0,1><<<gF, 256, GEMM_SMEM>>>(h_, w1T, bf1, lidx, nullptr, ff_, S_, D_, F_);
    // FFN2 + residual(out) -> final
    gemm_mma<0,1,0><<<gD, 256, GEMM_SMEM>>>(ff_, w2T, bf2, lidx, out, out, S_, F_, D_);
}

// round 10
// speedup vs baseline: 3.1499x; 1.7812x over previous
#include <cuda_runtime.h>
#include <cuda_fp16.h>
#include <math.h>
#include <stdint.h>

// Problem dims
#define L_  8
#define B_  8
#define S_  2048
#define D_  1024
#define H_  16
#define DH_ 64
#define F_  4096

// ---------------------------------------------------------------------------
// Scratch (__device__ globals; allocation-guard-safe)
// ---------------------------------------------------------------------------
__device__ __half g_h   [(size_t)B_ * S_ * D_];
__device__ __half g_q   [(size_t)B_ * S_ * D_];
__device__ __half g_k   [(size_t)B_ * S_ * D_];
__device__ __half g_vT  [(size_t)B_ * H_ * DH_ * S_];
__device__ __half g_attn[(size_t)B_ * S_ * D_];
__device__ __half g_ffn [(size_t)B_ * S_ * F_];
// Transposed + fp16-rounded weights: Wt[l][n][k]
__device__ __half g_WqT[(size_t)L_ * D_ * D_];
__device__ __half g_WkT[(size_t)L_ * D_ * D_];
__device__ __half g_WvT[(size_t)L_ * D_ * D_];
__device__ __half g_WoT[(size_t)L_ * D_ * D_];
__device__ __half g_W1T[(size_t)L_ * D_ * F_];
__device__ __half g_W2T[(size_t)L_ * F_ * D_];

// ---------------------------------------------------------------------------
// Helpers (baseline PTX only)
// ---------------------------------------------------------------------------
__device__ __forceinline__ uint32_t smem_u32(const void* p) {
    uint32_t a;
    asm("{ .reg .u64 t; cvta.to.shared.u64 t, %1; cvt.u32.u64 %0, t; }"
        : "=r"(a) : "l"(p));
    return a;
}

__device__ __forceinline__ uint32_t pack_f16(float lo, float hi) {
    uint32_t r;   // d.hi = cvt(%1), d.lo = cvt(%2)
    asm("cvt.rn.f16x2.f32 %0, %1, %2;" : "=r"(r) : "f"(hi), "f"(lo));
    return r;
}

#define SMEM_SWZ128(o) ((o) ^ (((o) >> 3) & 0x70))

#define CP_ASYNC16(dst_u32, src_ptr) \
    asm volatile("cp.async.cg.shared.global [%0], [%1], 16;" \
                 :: "r"(dst_u32), "l"(src_ptr))
#define CP_ASYNC_COMMIT() asm volatile("cp.async.commit_group;" ::: "memory")
#define CP_ASYNC_WAIT1()  asm volatile("cp.async.wait_group 1;" ::: "memory")
#define CP_ASYNC_WAIT0()  asm volatile("cp.async.wait_group 0;" ::: "memory")

__device__ __forceinline__ void ldsm_x4(uint32_t (&r)[4], uint32_t addr) {
    asm volatile("ldmatrix.sync.aligned.m8n8.x4.shared.b16 {%0,%1,%2,%3}, [%4];"
                 : "=r"(r[0]), "=r"(r[1]), "=r"(r[2]), "=r"(r[3]) : "r"(addr));
}

__device__ __forceinline__ void mma_f16(float (&d)[4],
                                        const uint32_t (&a)[4],
                                        uint32_t b0, uint32_t b1) {
    asm volatile(
        "mma.sync.aligned.m16n8k16.row.col.f32.f16.f16.f32 "
        "{%0,%1,%2,%3}, {%4,%5,%6,%7}, {%8,%9}, {%0,%1,%2,%3};"
        : "+f"(d[0]), "+f"(d[1]), "+f"(d[2]), "+f"(d[3])
        : "r"(a[0]), "r"(a[1]), "r"(a[2]), "r"(a[3]), "r"(b0), "r"(b1));
}

__device__ __forceinline__ float gelu_f(float x)
{
    float t = 0.7978845608028654f * (x + 0.044715f * x * x * x);
    float th;
    asm("tanh.approx.f32 %0, %1;" : "=f"(th) : "f"(t));
    return 0.5f * x * (1.0f + th);
}

// ---------------------------------------------------------------------------
// Weight transpose + fp16 RN round: W[l][K][N] fp32 -> Wt[l][N][K] fp16
// ---------------------------------------------------------------------------
__global__ __launch_bounds__(256) void transpose_round_kernel(
    const float* __restrict__ W, __half* __restrict__ Wt, int Kd, int Nd)
{
    __shared__ float t[32][33];
    int l  = blockIdx.z;
    int n0 = blockIdx.x * 32;
    int k0 = blockIdx.y * 32;
    const float* Wl = W + (size_t)l * Kd * Nd;
    __half* Wtl = Wt + (size_t)l * Nd * Kd;
    int c = threadIdx.x, r0 = threadIdx.y;
    #pragma unroll
    for (int i = 0; i < 4; i++) {
        int r = r0 + i * 8;
        t[r][c] = Wl[(size_t)(k0 + r) * Nd + n0 + c];
    }
    __syncthreads();
    #pragma unroll
    for (int i = 0; i < 4; i++) {
        int r = r0 + i * 8;
        Wtl[(size_t)(n0 + r) * Kd + k0 + c] = __float2half_rn(t[c][r]);
    }
}

// ---------------------------------------------------------------------------
// LayerNorm: fp32 in -> fp16 out (feeds tensor-core GEMMs)
// ---------------------------------------------------------------------------
__global__ __launch_bounds__(256) void ln_kernel(
    const float* __restrict__ X,
    const float* __restrict__ sall, const float* __restrict__ ball,
    const int* __restrict__ lidx, __half* __restrict__ Y)
{
    int row = blockIdx.x;
    int b   = row / S_;
    int tid = threadIdx.x;

    float4 xv = ((const float4*)(X + (size_t)row * D_))[tid];
    float s  = xv.x + xv.y + xv.z + xv.w;
    float ss = xv.x*xv.x + xv.y*xv.y + xv.z*xv.z + xv.w*xv.w;
    #pragma unroll
    for (int o = 16; o > 0; o >>= 1) {
        s  += __shfl_xor_sync(0xffffffffu, s,  o);
        ss += __shfl_xor_sync(0xffffffffu, ss, o);
    }
    __shared__ float rs[8], rss[8], mv[2];
    int wid = tid >> 5, lane = tid & 31;
    if (lane == 0) { rs[wid] = s; rss[wid] = ss; }
    __syncthreads();
    if (tid == 0) {
        float a = 0.f, c = 0.f;
        #pragma unroll
        for (int w = 0; w < 8; w++) { a += rs[w]; c += rss[w]; }
        float mean = a * (1.0f / D_);
        float var  = c * (1.0f / D_) - mean * mean;
        mv[0] = mean; mv[1] = rsqrtf(var + 1e-5f);
    }
    __syncthreads();
    float mean = mv[0], rstd = mv[1];

    int li = lidx[b];
    float4 sv = ((const float4*)(sall + (size_t)li * D_))[tid];
    float4 bv = ((const float4*)(ball + (size_t)li * D_))[tid];
    uint2 o;
    o.x = pack_f16((xv.x - mean) * rstd * sv.x + bv.x,
                   (xv.y - mean) * rstd * sv.y + bv.y);
    o.y = pack_f16((xv.z - mean) * rstd * sv.z + bv.z,
                   (xv.w - mean) * rstd * sv.w + bv.w);
    *(uint2*)&Y[(size_t)row * D_ + tid * 4] = o;
}

// ---------------------------------------------------------------------------
// Shared fp16 GEMM mainloop: 128x128 tile, BK=64 (128B rows), 8 warps (2x4),
// warp 64x32 of m16n8k16. 3-stage cp.async ring, SW128 swizzle.
// ---------------------------------------------------------------------------
#define GEMM_SMEM (1024 + 3 * 32768)

__device__ __forceinline__ void gemm_mainloop(
    const __half* __restrict__ Ag, const __half* __restrict__ Bg,
    int K, uint32_t sbase, int tid, int wm, int wn, int lane,
    float (&acc)[4][4][4])
{
    #pragma unroll
    for (int i = 0; i < 4; i++)
        #pragma unroll
        for (int j = 0; j < 4; j++)
            #pragma unroll
            for (int q = 0; q < 4; q++) acc[i][j][q] = 0.f;

    auto load_stage = [&](int kc, int stg) {
        uint32_t sA = sbase + (uint32_t)stg * 32768u;
        uint32_t sB = sA + 16384u;
        const __half* Ak = Ag + kc * 64;
        const __half* Bk = Bg + kc * 64;
        #pragma unroll
        for (int p = 0; p < 4; p++) {
            int idx = tid + p * 256;
            int r  = idx >> 3;
            int j  = idx & 7;                   // 16B chunk = 8 fp16
            uint32_t sw = SMEM_SWZ128((uint32_t)(r * 128 + j * 16));
            CP_ASYNC16(sA + sw, Ak + (size_t)r * K + j * 8);
            CP_ASYNC16(sB + sw, Bk + (size_t)r * K + j * 8);
        }
        CP_ASYNC_COMMIT();
    };

    int nk = K >> 6;
    load_stage(0, 0);
    if (nk > 1) load_stage(1, 1);

    int lr = lane & 15;
    int lh = (lane >> 4) * 16;

    for (int i = 0; i < nk; i++) {
        if (i < nk - 2) CP_ASYNC_WAIT1(); else CP_ASYNC_WAIT0();
        __syncthreads();
        if (i + 2 < nk) load_stage(i + 2, (i + 2) % 3);

        uint32_t sA = sbase + (uint32_t)(i % 3) * 32768u;
        uint32_t sB = sA + 16384u;

        #pragma unroll
        for (int ks = 0; ks < 4; ks++) {        // k16 steps (32B each)
            uint32_t afr[4][4];
            uint32_t bfr[2][4];
            #pragma unroll
            for (int mf = 0; mf < 4; mf++) {
                uint32_t off = (uint32_t)((64 * wm + 16 * mf + lr) * 128
                                          + ks * 32 + lh);
                ldsm_x4(afr[mf], sA + SMEM_SWZ128(off));
            }
            #pragma unroll
            for (int bf = 0; bf < 2; bf++) {
                uint32_t off = (uint32_t)((32 * wn + 16 * bf + lr) * 128
                                          + ks * 32 + lh);
                ldsm_x4(bfr[bf], sB + SMEM_SWZ128(off));
            }
            #pragma unroll
            for (int mf = 0; mf < 4; mf++)
                #pragma unroll
                for (int nf = 0; nf < 4; nf++)
                    mma_f16(acc[mf][nf], afr[mf],
                            bfr[nf >> 1][nf & 1], bfr[nf >> 1][2 + (nf & 1)]);
        }
    }
}

// ---------------------------------------------------------------------------
// Generic GEMM: C[b] = A[b](MxK)fp16 @ Wt[lidx[b]](NxK)^T fp16 + bias
//   ACT: gelu.  RES: +fp32 residual.  OUTH: C fp16 (else fp32).
// ---------------------------------------------------------------------------
template <int ACT, int RES, int OUTH>
__global__ __launch_bounds__(256, 2)
void gemm_mma(const __half* __restrict__ A,
              const __half* __restrict__ WT,
              const float* __restrict__ biasall, const int* __restrict__ lidx,
              const float* __restrict__ Res, void* __restrict__ Cv,
              int M, int K, int N)
{
    extern __shared__ __align__(16) char smraw[];
    uint32_t sbase = (smem_u32(smraw) + 1023u) & ~1023u;

    int tid  = threadIdx.x;
    int wid  = tid >> 5;
    int lane = tid & 31;
    int wm   = wid >> 2;
    int wn   = wid & 3;
    int b    = blockIdx.z;
    int li   = lidx[b];
    int row0 = blockIdx.y * 128;
    int col0 = blockIdx.x * 128;

    const __half* Ag = A  + (size_t)b  * M * K + (size_t)row0 * K;
    const __half* Bg = WT + (size_t)li * N * K + (size_t)col0 * K;

    float acc[4][4][4];
    gemm_mainloop(Ag, Bg, K, sbase, tid, wm, wn, lane, acc);

    int qr = lane >> 2;
    int qc = (lane & 3) * 2;
    const float* bp = biasall + (size_t)li * N;
    #pragma unroll
    for (int mf = 0; mf < 4; mf++) {
        int r = row0 + 64 * wm + 16 * mf + qr;
        #pragma unroll
        for (int nf = 0; nf < 4; nf++) {
            int cc = col0 + 32 * wn + 8 * nf + qc;
            #pragma unroll
            for (int half = 0; half < 2; half++) {
                int rr = r + half * 8;
                float v0 = acc[mf][nf][half * 2 + 0] + bp[cc + 0];
                float v1 = acc[mf][nf][half * 2 + 1] + bp[cc + 1];
                if (ACT) { v0 = gelu_f(v0); v1 = gelu_f(v1); }
                if (RES) {
                    float2 rv = *(const float2*)&Res[(size_t)b * M * N
                                                     + (size_t)rr * N + cc];
                    v0 += rv.x; v1 += rv.y;
                }
                size_t eo = (size_t)b * M * N + (size_t)rr * N + cc;
                if (OUTH) {
                    *(uint32_t*)&((__half*)Cv)[eo] = pack_f16(v0, v1);
                } else {
                    *(float2*)&((float*)Cv)[eo] = make_float2(v0, v1);
                }
            }
        }
    }
}

// ---------------------------------------------------------------------------
// Fused QKV GEMM (grid.x = 24): Q,K row-major fp16; V transposed per head.
// ---------------------------------------------------------------------------
__global__ __launch_bounds__(256, 2)
void gemm_qkv(const __half* __restrict__ A,
              const __half* __restrict__ WqT,
              const __half* __restrict__ WkT,
              const __half* __restrict__ WvT,
              const float* __restrict__ bqa, const float* __restrict__ bka,
              const float* __restrict__ bva,
              const int* __restrict__ lidx,
              __half* __restrict__ Oq, __half* __restrict__ Ok,
              __half* __restrict__ OvT)
{
    extern __shared__ __align__(16) char smraw[];
    uint32_t sbase = (smem_u32(smraw) + 1023u) & ~1023u;

    const int M = S_, K = D_, N = D_;
    int tid  = threadIdx.x;
    int wid  = tid >> 5;
    int lane = tid & 31;
    int wm   = wid >> 2;
    int wn   = wid & 3;
    int b    = blockIdx.z;
    int li   = lidx[b];
    int row0 = blockIdx.y * 128;
    int mat  = blockIdx.x >> 3;
    int col0 = (blockIdx.x & 7) * 128;

    const __half* WT = (mat == 0) ? WqT : (mat == 1) ? WkT : WvT;
    const float* ba = (mat == 0) ? bqa : (mat == 1) ? bka : bva;

    const __half* Ag = A  + (size_t)b  * M * K + (size_t)row0 * K;
    const __half* Bg = WT + (size_t)li * N * K + (size_t)col0 * K;

    float acc[4][4][4];
    gemm_mainloop(Ag, Bg, K, sbase, tid, wm, wn, lane, acc);

    int qr = lane >> 2;
    int qc = (lane & 3) * 2;
    const float* bp = ba + (size_t)li * N;

    if (mat < 2) {
        __half* C = (mat == 0) ? Oq : Ok;
        #pragma unroll
        for (int mf = 0; mf < 4; mf++) {
            int r = row0 + 64 * wm + 16 * mf + qr;
            #pragma unroll
            for (int nf = 0; nf < 4; nf++) {
                int cc = col0 + 32 * wn + 8 * nf + qc;
                #pragma unroll
                for (int half = 0; half < 2; half++) {
                    int rr = r + half * 8;
                    float v0 = acc[mf][nf][half * 2 + 0] + bp[cc + 0];
                    float v1 = acc[mf][nf][half * 2 + 1] + bp[cc + 1];
                    *(uint32_t*)&C[(size_t)b * M * N + (size_t)rr * N + cc] =
                        pack_f16(v0, v1);
                }
            }
        }
    } else {
        #pragma unroll
        for (int mf = 0; mf < 4; mf++) {
            int r = row0 + 64 * wm + 16 * mf + qr;
            #pragma unroll
            for (int nf = 0; nf < 4; nf++) {
                int cc = col0 + 32 * wn + 8 * nf + qc;
                #pragma unroll
                for (int half = 0; half < 2; half++) {
                    int rr = r + half * 8;
                    float v0 = acc[mf][nf][half * 2 + 0] + bp[cc + 0];
                    float v1 = acc[mf][nf][half * 2 + 1] + bp[cc + 1];
                    size_t hb = ((size_t)(b * H_ + (cc >> 6)) * DH_ + (cc & 63))
                                * (size_t)M + rr;
                    OvT[hb] = __float2half_rn(v0);
                    OvT[hb + (size_t)M] = __float2half_rn(v1);
                }
            }
        }
    }
}

// ---------------------------------------------------------------------------
// Flash attention on mma.sync fp16 (m16n8k16). 128 q-rows x (b,h), 8 warps.
// 144B padded rows (conflict-free ldmatrix). Split K/V commit groups.
// ---------------------------------------------------------------------------
#define ATT_ROWB 144u
#define ATT_SMEM ((128 + 64 + 64 + 128) * 144)

__global__ __launch_bounds__(256, 2) void attention_mma(
    const __half* __restrict__ Q, const __half* __restrict__ K,
    const __half* __restrict__ VT, __half* __restrict__ O)
{
    extern __shared__ __align__(16) char asmem[];
    uint32_t sm_q = smem_u32(asmem);
    uint32_t sm_k = sm_q + 128 * ATT_ROWB;
    uint32_t sm_v = sm_k + 64 * ATT_ROWB;
    uint32_t sm_p = sm_v + 64 * ATT_ROWB;

    int tid  = threadIdx.x;
    int wid  = tid >> 5;
    int lane = tid & 31;
    int q0   = blockIdx.x * 128;
    int h    = blockIdx.y;
    int b    = blockIdx.z;
    int lr   = lane & 15;
    int lh   = (lane >> 4) * 16;
    int qr   = lane >> 2;
    int qc   = (lane & 3) * 2;

    // Q tile (128 rows x 64 fp16 = 128B rows), group 0
    const __half* Qg = Q + ((size_t)b * S_ + q0) * D_ + h * DH_;
    #pragma unroll
    for (int p = 0; p < 4; p++) {
        int idx = tid + p * 256;
        int r = idx >> 3, j = idx & 7;
        CP_ASYNC16(sm_q + (uint32_t)r * ATT_ROWB + j * 16,
                   Qg + (size_t)r * D_ + j * 8);
    }
    CP_ASYNC_COMMIT();

    float ofr[8][4];
    #pragma unroll
    for (int nf = 0; nf < 8; nf++)
        #pragma unroll
        for (int q = 0; q < 4; q++) ofr[nf][q] = 0.f;
    float m0 = -1e30f, m1 = -1e30f, l0 = 0.f, l1 = 0.f;

    const __half* Kg = K  + (size_t)b * S_ * D_ + h * DH_;
    const __half* Vg = VT + (size_t)(b * H_ + h) * DH_ * S_;

    uint32_t arow = sm_q + (uint32_t)(16 * wid + lr) * ATT_ROWB + lh;
    uint32_t prow = sm_p + (uint32_t)(16 * wid + lr) * ATT_ROWB + lh;
    uint32_t pst0 = sm_p + (uint32_t)(16 * wid + qr) * ATT_ROWB + qc * 2;
    uint32_t pst1 = pst0 + 8 * ATT_ROWB;

    for (int t = 0; t < S_ / 64; t++) {
        int k0 = t * 64;
        // K tile (64 x 128B), own group
        #pragma unroll
        for (int p = 0; p < 2; p++) {
            int idx = tid + p * 256;
            int r = idx >> 3, j = idx & 7;
            CP_ASYNC16(sm_k + (uint32_t)r * ATT_ROWB + j * 16,
                       Kg + (size_t)(k0 + r) * D_ + j * 8);
        }
        CP_ASYNC_COMMIT();
        // V tile (64 dh-rows x 64 kv fp16 = 128B), separate group
        #pragma unroll
        for (int p = 0; p < 2; p++) {
            int idx = tid + p * 256;
            int r = idx >> 3, j = idx & 7;
            CP_ASYNC16(sm_v + (uint32_t)r * ATT_ROWB + j * 16,
                       Vg + (size_t)r * S_ + k0 + j * 8);
        }
        CP_ASYNC_COMMIT();
        CP_ASYNC_WAIT1();          // Q(t==0) + K done; V in flight
        __syncthreads();

        // S = Q K^T   (4 k16 steps over DH=64)
        float sfr[8][4];
        #pragma unroll
        for (int nf = 0; nf < 8; nf++)
            #pragma unroll
            for (int q = 0; q < 4; q++) sfr[nf][q] = 0.f;

        #pragma unroll
        for (int ks = 0; ks < 4; ks++) {
            uint32_t afr[4], bfr[4][4];
            ldsm_x4(afr, arow + ks * 32);
            #pragma unroll
            for (int bf = 0; bf < 4; bf++)
                ldsm_x4(bfr[bf], sm_k + (uint32_t)(16 * bf + lr) * ATT_ROWB
                                   + ks * 32 + lh);
            #pragma unroll
            for (int nf = 0; nf < 8; nf++)
                mma_f16(sfr[nf], afr,
                        bfr[nf >> 1][nf & 1], bfr[nf >> 1][2 + (nf & 1)]);
        }

        // scale + online softmax (rows qr, qr+8)
        float mt0 = -1e30f, mt1 = -1e30f;
        #pragma unroll
        for (int nf = 0; nf < 8; nf++) {
            #pragma unroll
            for (int q = 0; q < 4; q++) sfr[nf][q] *= 0.125f;
            mt0 = fmaxf(mt0, fmaxf(sfr[nf][0], sfr[nf][1]));
            mt1 = fmaxf(mt1, fmaxf(sfr[nf][2], sfr[nf][3]));
        }
        mt0 = fmaxf(mt0, __shfl_xor_sync(0xffffffffu, mt0, 1));
        mt0 = fmaxf(mt0, __shfl_xor_sync(0xffffffffu, mt0, 2));
        mt1 = fmaxf(mt1, __shfl_xor_sync(0xffffffffu, mt1, 1));
        mt1 = fmaxf(mt1, __shfl_xor_sync(0xffffffffu, mt1, 2));
        float mn0 = fmaxf(m0, mt0), mn1 = fmaxf(m1, mt1);
        float c0 = __expf(m0 - mn0), c1 = __expf(m1 - mn1);
        float s0 = 0.f, s1 = 0.f;
        #pragma unroll
        for (int nf = 0; nf < 8; nf++) {
            float p0 = __expf(sfr[nf][0] - mn0);
            float p1 = __expf(sfr[nf][1] - mn0);
            float p2 = __expf(sfr[nf][2] - mn1);
            float p3 = __expf(sfr[nf][3] - mn1);
            s0 += p0 + p1; s1 += p2 + p3;
            asm volatile("st.shared.b32 [%0], %1;"
                         :: "r"(pst0 + nf * 16), "r"(pack_f16(p0, p1)));
            asm volatile("st.shared.b32 [%0], %1;"
                         :: "r"(pst1 + nf * 16), "r"(pack_f16(p2, p3)));
        }
        s0 += __shfl_xor_sync(0xffffffffu, s0, 1);
        s0 += __shfl_xor_sync(0xffffffffu, s0, 2);
        s1 += __shfl_xor_sync(0xffffffffu, s1, 1);
        s1 += __shfl_xor_sync(0xffffffffu, s1, 2);
        l0 = l0 * c0 + s0;  l1 = l1 * c1 + s1;
        m0 = mn0;  m1 = mn1;
        #pragma unroll
        for (int nf = 0; nf < 8; nf++) {
            ofr[nf][0] *= c0; ofr[nf][1] *= c0;
            ofr[nf][2] *= c1; ofr[nf][3] *= c1;
        }
        __syncwarp();

        CP_ASYNC_WAIT0();          // V arrived
        __syncthreads();

        // O += P V   (4 k16 steps over kv=64)
        #pragma unroll
        for (int ks = 0; ks < 4; ks++) {
            uint32_t afr[4], bfr[4][4];
            ldsm_x4(afr, prow + ks * 32);
            #pragma unroll
            for (int bf = 0; bf < 4; bf++)
                ldsm_x4(bfr[bf], sm_v + (uint32_t)(16 * bf + lr) * ATT_ROWB
                                   + ks * 32 + lh);
            #pragma unroll
            for (int nf = 0; nf < 8; nf++)
                mma_f16(ofr[nf], afr,
                        bfr[nf >> 1][nf & 1], bfr[nf >> 1][2 + (nf & 1)]);
        }
        __syncthreads();
    }

    // Normalize + store fp16 (feeds Wo GEMM)
    float i0 = 1.f / l0, i1 = 1.f / l1;
    __half* Og = O + ((size_t)b * S_ + q0) * D_ + h * DH_;
    int r0 = 16 * wid + qr;
    #pragma unroll
    for (int nf = 0; nf < 8; nf++) {
        int cc = 8 * nf + qc;
        *(uint32_t*)&Og[(size_t)r0 * D_ + cc] =
            pack_f16(ofr[nf][0] * i0, ofr[nf][1] * i0);
        *(uint32_t*)&Og[(size_t)(r0 + 8) * D_ + cc] =
            pack_f16(ofr[nf][2] * i1, ofr[nf][3] * i1);
    }
}

// ---------------------------------------------------------------------------
// Launch
// ---------------------------------------------------------------------------
extern "C" void kernel_launch(void* const* d_in, const int* in_sizes, int n_in,
                              void* d_out, int out_size)
{
    (void)in_sizes; (void)n_in; (void)out_size;
    const float* x    = (const float*)d_in[0];
    const int*   lidx = (const int*)  d_in[1];
    const float* Wq = (const float*)d_in[2];  const float* bq = (const float*)d_in[3];
    const float* Wk = (const float*)d_in[4];  const float* bk = (const float*)d_in[5];
    const float* Wv = (const float*)d_in[6];  const float* bv = (const float*)d_in[7];
    const float* Wo = (const float*)d_in[8];  const float* bo = (const float*)d_in[9];
    const float* s1 = (const float*)d_in[10]; const float* b1n = (const float*)d_in[11];
    const float* s2 = (const float*)d_in[12]; const float* b2n = (const float*)d_in[13];
    const float* W1 = (const float*)d_in[14]; const float* bf1 = (const float*)d_in[15];
    const float* W2 = (const float*)d_in[16]; const float* bf2 = (const float*)d_in[17];
    float* out = (float*)d_out;

    __half *h_, *q_, *k_, *vT_, *at_, *ff_;
    __half *wqT, *wkT, *wvT, *woT, *w1T, *w2T;
    cudaGetSymbolAddress((void**)&h_,  g_h);
    cudaGetSymbolAddress((void**)&q_,  g_q);
    cudaGetSymbolAddress((void**)&k_,  g_k);
    cudaGetSymbolAddress((void**)&vT_, g_vT);
    cudaGetSymbolAddress((void**)&at_, g_attn);
    cudaGetSymbolAddress((void**)&ff_, g_ffn);
    cudaGetSymbolAddress((void**)&wqT, g_WqT);
    cudaGetSymbolAddress((void**)&wkT, g_WkT);
    cudaGetSymbolAddress((void**)&wvT, g_WvT);
    cudaGetSymbolAddress((void**)&woT, g_WoT);
    cudaGetSymbolAddress((void**)&w1T, g_W1T);
    cudaGetSymbolAddress((void**)&w2T, g_W2T);

    cudaFuncSetAttribute(attention_mma,
                         cudaFuncAttributeMaxDynamicSharedMemorySize, ATT_SMEM);
    cudaFuncSetAttribute(gemm_qkv,
                         cudaFuncAttributeMaxDynamicSharedMemorySize, GEMM_SMEM);
    cudaFuncSetAttribute(gemm_mma<0,1,0>,
                         cudaFuncAttributeMaxDynamicSharedMemorySize, GEMM_SMEM);
    cudaFuncSetAttribute(gemm_mma<1,0,1>,
                         cudaFuncAttributeMaxDynamicSharedMemorySize, GEMM_SMEM);

    // Weight transpose + fp16 rounding
    dim3 tb(32, 8);
    transpose_round_kernel<<<dim3(D_/32, D_/32, L_), tb>>>(Wq, wqT, D_, D_);
    transpose_round_kernel<<<dim3(D_/32, D_/32, L_), tb>>>(Wk, wkT, D_, D_);
    transpose_round_kernel<<<dim3(D_/32, D_/32, L_), tb>>>(Wv, wvT, D_, D_);
    transpose_round_kernel<<<dim3(D_/32, D_/32, L_), tb>>>(Wo, woT, D_, D_);
    transpose_round_kernel<<<dim3(F_/32, D_/32, L_), tb>>>(W1, w1T, D_, F_);
    transpose_round_kernel<<<dim3(D_/32, F_/32, L_), tb>>>(W2, w2T, F_, D_);

    dim3 gD(D_ / 128, S_ / 128, B_);
    dim3 gF(F_ / 128, S_ / 128, B_);

    // LN1 -> h (fp16)
    ln_kernel<<<B_ * S_, 256>>>(x, s1, b1n, lidx, h_);
    // Fused QKV; V written transposed (all fp16)
    gemm_qkv<<<dim3(24, S_ / 128, B_), 256, GEMM_SMEM>>>(
        h_, wqT, wkT, wvT, bq, bk, bv, lidx, q_, k_, vT_);
    // Attention (fp16 tensor-core)
    attention_mma<<<dim3(S_ / 128, H_, B_), 256, ATT_SMEM>>>(q_, k_, vT_, at_);
    // O-proj + residual(x) -> out (fp32)
    gemm_mma<0,1,0><<<gD, 256, GEMM_SMEM>>>(at_, woT, bo, lidx, x, out,
                                            S_, D_, D_);
    // LN2 -> h (fp16)
    ln_kernel<<<B_ * S_, 256>>>(out, s2, b2n, lidx, h_);
    // FFN1 + GELU -> ff (fp16)
    gemm_mma<1,0,1><<<gF, 256, GEMM_SMEM>>>(h_, w1T, bf1, lidx, nullptr, ff_,
                                            S_, D_, F_);
    // FFN2 + residual(out) -> final (fp32)
    gemm_mma<0,1,0><<<gD, 256, GEMM_SMEM>>>(ff_, w2T, bf2, lidx, out, out,
                                            S_, F_, D_);
}

// round 11
// speedup vs baseline: 3.2449x; 1.0302x over previous
#include <cuda_runtime.h>
#include <cuda_fp16.h>
#include <math.h>
#include <stdint.h>

// Problem dims
#define L_  8
#define B_  8
#define S_  2048
#define D_  1024
#define H_  16
#define DH_ 64
#define F_  4096

// ---------------------------------------------------------------------------
// Scratch (__device__ globals; allocation-guard-safe)
// ---------------------------------------------------------------------------
__device__ __half g_h   [(size_t)B_ * S_ * D_];
__device__ __half g_q   [(size_t)B_ * S_ * D_];
__device__ __half g_k   [(size_t)B_ * S_ * D_];
__device__ __half g_vT  [(size_t)B_ * H_ * DH_ * S_];
__device__ __half g_attn[(size_t)B_ * S_ * D_];
__device__ __half g_ffn [(size_t)B_ * S_ * F_];
// Transposed + fp16-rounded weights: Wt[l][n][k]
__device__ __half g_WqT[(size_t)L_ * D_ * D_];
__device__ __half g_WkT[(size_t)L_ * D_ * D_];
__device__ __half g_WvT[(size_t)L_ * D_ * D_];
__device__ __half g_WoT[(size_t)L_ * D_ * D_];
__device__ __half g_W1T[(size_t)L_ * D_ * F_];
__device__ __half g_W2T[(size_t)L_ * F_ * D_];

// ---------------------------------------------------------------------------
// Helpers (baseline PTX only)
// ---------------------------------------------------------------------------
__device__ __forceinline__ uint32_t smem_u32(const void* p) {
    uint32_t a;
    asm("{ .reg .u64 t; cvta.to.shared.u64 t, %1; cvt.u32.u64 %0, t; }"
        : "=r"(a) : "l"(p));
    return a;
}

__device__ __forceinline__ uint32_t pack_f16(float lo, float hi) {
    uint32_t r;   // d.hi = cvt(%1), d.lo = cvt(%2)
    asm("cvt.rn.f16x2.f32 %0, %1, %2;" : "=r"(r) : "f"(hi), "f"(lo));
    return r;
}

#define SMEM_SWZ128(o) ((o) ^ (((o) >> 3) & 0x70))

#define CP_ASYNC16(dst_u32, src_ptr) \
    asm volatile("cp.async.cg.shared.global [%0], [%1], 16;" \
                 :: "r"(dst_u32), "l"(src_ptr))
#define CP_ASYNC_COMMIT() asm volatile("cp.async.commit_group;" ::: "memory")
#define CP_ASYNC_WAIT1()  asm volatile("cp.async.wait_group 1;" ::: "memory")
#define CP_ASYNC_WAIT0()  asm volatile("cp.async.wait_group 0;" ::: "memory")

__device__ __forceinline__ void ldsm_x4(uint32_t (&r)[4], uint32_t addr) {
    asm volatile("ldmatrix.sync.aligned.m8n8.x4.shared.b16 {%0,%1,%2,%3}, [%4];"
                 : "=r"(r[0]), "=r"(r[1]), "=r"(r[2]), "=r"(r[3]) : "r"(addr));
}

__device__ __forceinline__ void mma_f16(float (&d)[4],
                                        const uint32_t (&a)[4],
                                        uint32_t b0, uint32_t b1) {
    asm volatile(
        "mma.sync.aligned.m16n8k16.row.col.f32.f16.f16.f32 "
        "{%0,%1,%2,%3}, {%4,%5,%6,%7}, {%8,%9}, {%0,%1,%2,%3};"
        : "+f"(d[0]), "+f"(d[1]), "+f"(d[2]), "+f"(d[3])
        : "r"(a[0]), "r"(a[1]), "r"(a[2]), "r"(a[3]), "r"(b0), "r"(b1));
}

__device__ __forceinline__ float gelu_f(float x)
{
    float t = 0.7978845608028654f * (x + 0.044715f * x * x * x);
    float th;
    asm("tanh.approx.f32 %0, %1;" : "=f"(th) : "f"(t));
    return 0.5f * x * (1.0f + th);
}

// ---------------------------------------------------------------------------
// 128x128 weight transpose+round macro-tile: W[l][Kd][Nd] fp32 -> Wt[l][Nd][Kd]
// fp16. One CTA (256 thr) per macro-tile; 16 sub-tiles of 32x32 via smem.
// ---------------------------------------------------------------------------
__device__ __forceinline__ void transpose_tile128(
    const float* __restrict__ W, __half* __restrict__ Wt,
    int Kd, int Nd, int l, int k0, int n0)
{
    __shared__ float tbuf[32][33];
    const float* Wl  = W  + (size_t)l * Kd * Nd;
    __half*      Wtl = Wt + (size_t)l * Nd * Kd;
    int c  = threadIdx.x & 31;
    int r0 = threadIdx.x >> 5;          // 0..7
    #pragma unroll
    for (int sub = 0; sub < 16; sub++) {
        int sk = k0 + (sub >> 2) * 32;
        int sn = n0 + (sub & 3) * 32;
        __syncthreads();
        #pragma unroll
        for (int i = 0; i < 4; i++)
            tbuf[r0 + 8 * i][c] = Wl[(size_t)(sk + r0 + 8 * i) * Nd + sn + c];
        __syncthreads();
        #pragma unroll
        for (int i = 0; i < 4; i++)
            Wtl[(size_t)(sn + r0 + 8 * i) * Kd + sk + c] =
                __float2half_rn(tbuf[c][r0 + 8 * i]);
    }
}

// ---------------------------------------------------------------------------
// LayerNorm body: fp32 in -> fp16 out
// ---------------------------------------------------------------------------
__device__ __forceinline__ void ln_body(
    const float* __restrict__ X,
    const float* __restrict__ sall, const float* __restrict__ ball,
    const int* __restrict__ lidx, __half* __restrict__ Y, int row)
{
    int b   = row / S_;
    int tid = threadIdx.x;

    float4 xv = ((const float4*)(X + (size_t)row * D_))[tid];
    float s  = xv.x + xv.y + xv.z + xv.w;
    float ss = xv.x*xv.x + xv.y*xv.y + xv.z*xv.z + xv.w*xv.w;
    #pragma unroll
    for (int o = 16; o > 0; o >>= 1) {
        s  += __shfl_xor_sync(0xffffffffu, s,  o);
        ss += __shfl_xor_sync(0xffffffffu, ss, o);
    }
    __shared__ float rs[8], rss[8], mv[2];
    int wid = tid >> 5, lane = tid & 31;
    if (lane == 0) { rs[wid] = s; rss[wid] = ss; }
    __syncthreads();
    if (tid == 0) {
        float a = 0.f, c = 0.f;
        #pragma unroll
        for (int w = 0; w < 8; w++) { a += rs[w]; c += rss[w]; }
        float mean = a * (1.0f / D_);
        float var  = c * (1.0f / D_) - mean * mean;
        mv[0] = mean; mv[1] = rsqrtf(var + 1e-5f);
    }
    __syncthreads();
    float mean = mv[0], rstd = mv[1];

    int li = lidx[b];
    float4 sv = ((const float4*)(sall + (size_t)li * D_))[tid];
    float4 bv = ((const float4*)(ball + (size_t)li * D_))[tid];
    uint2 o;
    o.x = pack_f16((xv.x - mean) * rstd * sv.x + bv.x,
                   (xv.y - mean) * rstd * sv.y + bv.y);
    o.y = pack_f16((xv.z - mean) * rstd * sv.z + bv.z,
                   (xv.w - mean) * rstd * sv.w + bv.w);
    *(uint2*)&Y[(size_t)row * D_ + tid * 4] = o;
}

// Plain LN (LN2)
__global__ __launch_bounds__(256) void ln_kernel(
    const float* __restrict__ X,
    const float* __restrict__ sall, const float* __restrict__ ball,
    const int* __restrict__ lidx, __half* __restrict__ Y)
{
    ln_body(X, sall, ball, lidx, Y, blockIdx.x);
}

// LN1 fused with Wq/Wk/Wv transpose+round (extra 1536 CTAs at grid tail)
__global__ __launch_bounds__(256) void ln1_fused_kernel(
    const float* __restrict__ X,
    const float* __restrict__ sall, const float* __restrict__ ball,
    const int* __restrict__ lidx, __half* __restrict__ Y,
    const float* __restrict__ Wq, const float* __restrict__ Wk,
    const float* __restrict__ Wv,
    __half* __restrict__ WqT, __half* __restrict__ WkT,
    __half* __restrict__ WvT)
{
    if (blockIdx.x >= B_ * S_) {
        int id  = blockIdx.x - B_ * S_;     // 0..1535
        int w   = id >> 9;                  // 0..2
        int t   = id & 511;
        int l   = t >> 6;
        int rem = t & 63;                   // 8x8 tiles of 128x128
        const float* W = (w == 0) ? Wq : (w == 1) ? Wk : Wv;
        __half* WT = (w == 0) ? WqT : (w == 1) ? WkT : WvT;
        transpose_tile128(W, WT, D_, D_, l, (rem >> 3) * 128, (rem & 7) * 128);
        return;
    }
    ln_body(X, sall, ball, lidx, Y, blockIdx.x);
}

// ---------------------------------------------------------------------------
// Shared fp16 GEMM mainloop: 128x128 tile, BK=64 (128B rows), 8 warps (2x4),
// warp 64x32 of m16n8k16. 3-stage cp.async ring, SW128 swizzle.
// ---------------------------------------------------------------------------
#define GEMM_SMEM (1024 + 3 * 32768)

__device__ __forceinline__ void gemm_mainloop(
    const __half* __restrict__ Ag, const __half* __restrict__ Bg,
    int K, uint32_t sbase, int tid, int wm, int wn, int lane,
    float (&acc)[4][4][4])
{
    #pragma unroll
    for (int i = 0; i < 4; i++)
        #pragma unroll
        for (int j = 0; j < 4; j++)
            #pragma unroll
            for (int q = 0; q < 4; q++) acc[i][j][q] = 0.f;

    auto load_stage = [&](int kc, int stg) {
        uint32_t sA = sbase + (uint32_t)stg * 32768u;
        uint32_t sB = sA + 16384u;
        const __half* Ak = Ag + kc * 64;
        const __half* Bk = Bg + kc * 64;
        #pragma unroll
        for (int p = 0; p < 4; p++) {
            int idx = tid + p * 256;
            int r  = idx >> 3;
            int j  = idx & 7;                   // 16B chunk = 8 fp16
            uint32_t sw = SMEM_SWZ128((uint32_t)(r * 128 + j * 16));
            CP_ASYNC16(sA + sw, Ak + (size_t)r * K + j * 8);
            CP_ASYNC16(sB + sw, Bk + (size_t)r * K + j * 8);
        }
        CP_ASYNC_COMMIT();
    };

    int nk = K >> 6;
    load_stage(0, 0);
    if (nk > 1) load_stage(1, 1);

    int lr = lane & 15;
    int lh = (lane >> 4) * 16;

    for (int i = 0; i < nk; i++) {
        if (i < nk - 2) CP_ASYNC_WAIT1(); else CP_ASYNC_WAIT0();
        __syncthreads();
        if (i + 2 < nk) load_stage(i + 2, (i + 2) % 3);

        uint32_t sA = sbase + (uint32_t)(i % 3) * 32768u;
        uint32_t sB = sA + 16384u;

        #pragma unroll
        for (int ks = 0; ks < 4; ks++) {        // k16 steps (32B each)
            uint32_t afr[4][4];
            uint32_t bfr[2][4];
            #pragma unroll
            for (int mf = 0; mf < 4; mf++) {
                uint32_t off = (uint32_t)((64 * wm + 16 * mf + lr) * 128
                                          + ks * 32 + lh);
                ldsm_x4(afr[mf], sA + SMEM_SWZ128(off));
            }
            #pragma unroll
            for (int bf = 0; bf < 2; bf++) {
                uint32_t off = (uint32_t)((32 * wn + 16 * bf + lr) * 128
                                          + ks * 32 + lh);
                ldsm_x4(bfr[bf], sB + SMEM_SWZ128(off));
            }
            #pragma unroll
            for (int mf = 0; mf < 4; mf++)
                #pragma unroll
                for (int nf = 0; nf < 4; nf++)
                    mma_f16(acc[mf][nf], afr[mf],
                            bfr[nf >> 1][nf & 1], bfr[nf >> 1][2 + (nf & 1)]);
        }
    }
}

// ---------------------------------------------------------------------------
// Generic GEMM: C[b] = A[b](MxK)fp16 @ Wt[lidx[b]](NxK)^T fp16 + bias
//   ACT: gelu.  RES: +fp32 residual.  OUTH: C fp16 (else fp32).
// ---------------------------------------------------------------------------
template <int ACT, int RES, int OUTH>
__global__ __launch_bounds__(256, 2)
void gemm_mma(const __half* __restrict__ A,
              const __half* __restrict__ WT,
              const float* __restrict__ biasall, const int* __restrict__ lidx,
              const float* __restrict__ Res, void* __restrict__ Cv,
              int M, int K, int N)
{
    extern __shared__ __align__(16) char smraw[];
    uint32_t sbase = (smem_u32(smraw) + 1023u) & ~1023u;

    int tid  = threadIdx.x;
    int wid  = tid >> 5;
    int lane = tid & 31;
    int wm   = wid >> 2;
    int wn   = wid & 3;
    int b    = blockIdx.z;
    int li   = lidx[b];
    int row0 = blockIdx.y * 128;
    int col0 = blockIdx.x * 128;

    const __half* Ag = A  + (size_t)b  * M * K + (size_t)row0 * K;
    const __half* Bg = WT + (size_t)li * N * K + (size_t)col0 * K;

    float acc[4][4][4];
    gemm_mainloop(Ag, Bg, K, sbase, tid, wm, wn, lane, acc);

    int qr = lane >> 2;
    int qc = (lane & 3) * 2;
    const float* bp = biasall + (size_t)li * N;
    #pragma unroll
    for (int mf = 0; mf < 4; mf++) {
        int r = row0 + 64 * wm + 16 * mf + qr;
        #pragma unroll
        for (int nf = 0; nf < 4; nf++) {
            int cc = col0 + 32 * wn + 8 * nf + qc;
            #pragma unroll
            for (int half = 0; half < 2; half++) {
                int rr = r + half * 8;
                float v0 = acc[mf][nf][half * 2 + 0] + bp[cc + 0];
                float v1 = acc[mf][nf][half * 2 + 1] + bp[cc + 1];
                if (ACT) { v0 = gelu_f(v0); v1 = gelu_f(v1); }
                if (RES) {
                    float2 rv = *(const float2*)&Res[(size_t)b * M * N
                                                     + (size_t)rr * N + cc];
                    v0 += rv.x; v1 += rv.y;
                }
                size_t eo = (size_t)b * M * N + (size_t)rr * N + cc;
                if (OUTH) {
                    *(uint32_t*)&((__half*)Cv)[eo] = pack_f16(v0, v1);
                } else {
                    *(float2*)&((float*)Cv)[eo] = make_float2(v0, v1);
                }
            }
        }
    }
}

// ---------------------------------------------------------------------------
// Fused QKV GEMM + Wo/W1/W2 transpose CTAs.
// grid (60, 16, 8): x<24 -> GEMM (mat = x/8, col-block = x%8);
// x>=24 -> transpose macro-tile id = (x-24) + 36*(y + 16*z), 4608 tiles:
//   [0,512)     Wo  (1024x1024, 64 tiles/layer)
//   [512,2560)  W1  (1024x4096, 256 tiles/layer)
//   [2560,4608) W2  (4096x1024, 256 tiles/layer)
// These outputs are consumed only by later kernel launches.
// ---------------------------------------------------------------------------
__global__ __launch_bounds__(256, 2)
void gemm_qkv(const __half* __restrict__ A,
              const __half* __restrict__ WqT,
              const __half* __restrict__ WkT,
              const __half* __restrict__ WvT,
              const float* __restrict__ bqa, const float* __restrict__ bka,
              const float* __restrict__ bva,
              const int* __restrict__ lidx,
              __half* __restrict__ Oq, __half* __restrict__ Ok,
              __half* __restrict__ OvT,
              const float* __restrict__ Wo, const float* __restrict__ W1,
              const float* __restrict__ W2,
              __half* __restrict__ WoT, __half* __restrict__ W1T,
              __half* __restrict__ W2T)
{
    extern __shared__ __align__(16) char smraw[];

    if (blockIdx.x >= 24) {
        int id = (blockIdx.x - 24) + 36 * (blockIdx.y + 16 * blockIdx.z);
        if (id < 512) {
            int l = id >> 6, rem = id & 63;
            transpose_tile128(Wo, WoT, D_, D_, l,
                              (rem >> 3) * 128, (rem & 7) * 128);
        } else if (id < 2560) {
            int t = id - 512;
            int l = t >> 8, rem = t & 255;       // 8 k-tiles x 32 n-tiles
            transpose_tile128(W1, W1T, D_, F_, l,
                              (rem >> 5) * 128, (rem & 31) * 128);
        } else {
            int t = id - 2560;
            int l = t >> 8, rem = t & 255;       // 32 k-tiles x 8 n-tiles
            transpose_tile128(W2, W2T, F_, D_, l,
                              (rem >> 3) * 128, (rem & 7) * 128);
        }
        return;
    }

    uint32_t sbase = (smem_u32(smraw) + 1023u) & ~1023u;

    const int M = S_, K = D_, N = D_;
    int tid  = threadIdx.x;
    int wid  = tid >> 5;
    int lane = tid & 31;
    int wm   = wid >> 2;
    int wn   = wid & 3;
    int b    = blockIdx.z;
    int li   = lidx[b];
    int row0 = blockIdx.y * 128;
    int mat  = blockIdx.x >> 3;
    int col0 = (blockIdx.x & 7) * 128;

    const __half* WT = (mat == 0) ? WqT : (mat == 1) ? WkT : WvT;
    const float* ba = (mat == 0) ? bqa : (mat == 1) ? bka : bva;

    const __half* Ag = A  + (size_t)b  * M * K + (size_t)row0 * K;
    const __half* Bg = WT + (size_t)li * N * K + (size_t)col0 * K;

    float acc[4][4][4];
    gemm_mainloop(Ag, Bg, K, sbase, tid, wm, wn, lane, acc);

    int qr = lane >> 2;
    int qc = (lane & 3) * 2;
    const float* bp = ba + (size_t)li * N;

    if (mat < 2) {
        __half* C = (mat == 0) ? Oq : Ok;
        #pragma unroll
        for (int mf = 0; mf < 4; mf++) {
            int r = row0 + 64 * wm + 16 * mf + qr;
            #pragma unroll
            for (int nf = 0; nf < 4; nf++) {
                int cc = col0 + 32 * wn + 8 * nf + qc;
                #pragma unroll
                for (int half = 0; half < 2; half++) {
                    int rr = r + half * 8;
                    float v0 = acc[mf][nf][half * 2 + 0] + bp[cc + 0];
                    float v1 = acc[mf][nf][half * 2 + 1] + bp[cc + 1];
                    *(uint32_t*)&C[(size_t)b * M * N + (size_t)rr * N + cc] =
                        pack_f16(v0, v1);
                }
            }
        }
    } else {
        #pragma unroll
        for (int mf = 0; mf < 4; mf++) {
            int r = row0 + 64 * wm + 16 * mf + qr;
            #pragma unroll
            for (int nf = 0; nf < 4; nf++) {
                int cc = col0 + 32 * wn + 8 * nf + qc;
                #pragma unroll
                for (int half = 0; half < 2; half++) {
                    int rr = r + half * 8;
                    float v0 = acc[mf][nf][half * 2 + 0] + bp[cc + 0];
                    float v1 = acc[mf][nf][half * 2 + 1] + bp[cc + 1];
                    size_t hb = ((size_t)(b * H_ + (cc >> 6)) * DH_ + (cc & 63))
                                * (size_t)M + rr;
                    OvT[hb] = __float2half_rn(v0);
                    OvT[hb + (size_t)M] = __float2half_rn(v1);
                }
            }
        }
    }
}

// ---------------------------------------------------------------------------
// Flash attention on mma.sync fp16 (m16n8k16). 128 q-rows x (b,h), 8 warps.
// 144B padded rows (conflict-free ldmatrix). Split K/V commit groups.
// ---------------------------------------------------------------------------
#define ATT_ROWB 144u
#define ATT_SMEM ((128 + 64 + 64 + 128) * 144)

__global__ __launch_bounds__(256, 2) void attention_mma(
    const __half* __restrict__ Q, const __half* __restrict__ K,
    const __half* __restrict__ VT, __half* __restrict__ O)
{
    extern __shared__ __align__(16) char asmem[];
    uint32_t sm_q = smem_u32(asmem);
    uint32_t sm_k = sm_q + 128 * ATT_ROWB;
    uint32_t sm_v = sm_k + 64 * ATT_ROWB;
    uint32_t sm_p = sm_v + 64 * ATT_ROWB;

    int tid  = threadIdx.x;
    int wid  = tid >> 5;
    int lane = tid & 31;
    int q0   = blockIdx.x * 128;
    int h    = blockIdx.y;
    int b    = blockIdx.z;
    int lr   = lane & 15;
    int lh   = (lane >> 4) * 16;
    int qr   = lane >> 2;
    int qc   = (lane & 3) * 2;

    // Q tile (128 rows x 64 fp16 = 128B rows), group 0
    const __half* Qg = Q + ((size_t)b * S_ + q0) * D_ + h * DH_;
    #pragma unroll
    for (int p = 0; p < 4; p++) {
        int idx = tid + p * 256;
        int r = idx >> 3, j = idx & 7;
        CP_ASYNC16(sm_q + (uint32_t)r * ATT_ROWB + j * 16,
                   Qg + (size_t)r * D_ + j * 8);
    }
    CP_ASYNC_COMMIT();

    float ofr[8][4];
    #pragma unroll
    for (int nf = 0; nf < 8; nf++)
        #pragma unroll
        for (int q = 0; q < 4; q++) ofr[nf][q] = 0.f;
    float m0 = -1e30f, m1 = -1e30f, l0 = 0.f, l1 = 0.f;

    const __half* Kg = K  + (size_t)b * S_ * D_ + h * DH_;
    const __half* Vg = VT + (size_t)(b * H_ + h) * DH_ * S_;

    uint32_t arow = sm_q + (uint32_t)(16 * wid + lr) * ATT_ROWB + lh;
    uint32_t prow = sm_p + (uint32_t)(16 * wid + lr) * ATT_ROWB + lh;
    uint32_t pst0 = sm_p + (uint32_t)(16 * wid + qr) * ATT_ROWB + qc * 2;
    uint32_t pst1 = pst0 + 8 * ATT_ROWB;

    for (int t = 0; t < S_ / 64; t++) {
        int k0 = t * 64;
        // K tile (64 x 128B), own group
        #pragma unroll
        for (int p = 0; p < 2; p++) {
            int idx = tid + p * 256;
            int r = idx >> 3, j = idx & 7;
            CP_ASYNC16(sm_k + (uint32_t)r * ATT_ROWB + j * 16,
                       Kg + (size_t)(k0 + r) * D_ + j * 8);
        }
        CP_ASYNC_COMMIT();
        // V tile (64 dh-rows x 64 kv fp16 = 128B), separate group
        #pragma unroll
        for (int p = 0; p < 2; p++) {
            int idx = tid + p * 256;
            int r = idx >> 3, j = idx & 7;
            CP_ASYNC16(sm_v + (uint32_t)r * ATT_ROWB + j * 16,
                       Vg + (size_t)r * S_ + k0 + j * 8);
        }
        CP_ASYNC_COMMIT();
        CP_ASYNC_WAIT1();          // Q(t==0) + K done; V in flight
        __syncthreads();

        // S = Q K^T   (4 k16 steps over DH=64)
        float sfr[8][4];
        #pragma unroll
        for (int nf = 0; nf < 8; nf++)
            #pragma unroll
            for (int q = 0; q < 4; q++) sfr[nf][q] = 0.f;

        #pragma unroll
        for (int ks = 0; ks < 4; ks++) {
            uint32_t afr[4], bfr[4][4];
            ldsm_x4(afr, arow + ks * 32);
            #pragma unroll
            for (int bf = 0; bf < 4; bf++)
                ldsm_x4(bfr[bf], sm_k + (uint32_t)(16 * bf + lr) * ATT_ROWB
                                   + ks * 32 + lh);
            #pragma unroll
            for (int nf = 0; nf < 8; nf++)
                mma_f16(sfr[nf], afr,
                        bfr[nf >> 1][nf & 1], bfr[nf >> 1][2 + (nf & 1)]);
        }

        // scale + online softmax (rows qr, qr+8)
        float mt0 = -1e30f, mt1 = -1e30f;
        #pragma unroll
        for (int nf = 0; nf < 8; nf++) {
            #pragma unroll
            for (int q = 0; q < 4; q++) sfr[nf][q] *= 0.125f;
            mt0 = fmaxf(mt0, fmaxf(sfr[nf][0], sfr[nf][1]));
            mt1 = fmaxf(mt1, fmaxf(sfr[nf][2], sfr[nf][3]));
        }
        mt0 = fmaxf(mt0, __shfl_xor_sync(0xffffffffu, mt0, 1));
        mt0 = fmaxf(mt0, __shfl_xor_sync(0xffffffffu, mt0, 2));
        mt1 = fmaxf(mt1, __shfl_xor_sync(0xffffffffu, mt1, 1));
        mt1 = fmaxf(mt1, __shfl_xor_sync(0xffffffffu, mt1, 2));
        float mn0 = fmaxf(m0, mt0), mn1 = fmaxf(m1, mt1);
        float c0 = __expf(m0 - mn0), c1 = __expf(m1 - mn1);
        float s0 = 0.f, s1 = 0.f;
        #pragma unroll
        for (int nf = 0; nf < 8; nf++) {
            float p0 = __expf(sfr[nf][0] - mn0);
            float p1 = __expf(sfr[nf][1] - mn0);
            float p2 = __expf(sfr[nf][2] - mn1);
            float p3 = __expf(sfr[nf][3] - mn1);
            s0 += p0 + p1; s1 += p2 + p3;
            asm volatile("st.shared.b32 [%0], %1;"
                         :: "r"(pst0 + nf * 16), "r"(pack_f16(p0, p1)));
            asm volatile("st.shared.b32 [%0], %1;"
                         :: "r"(pst1 + nf * 16), "r"(pack_f16(p2, p3)));
        }
        s0 += __shfl_xor_sync(0xffffffffu, s0, 1);
        s0 += __shfl_xor_sync(0xffffffffu, s0, 2);
        s1 += __shfl_xor_sync(0xffffffffu, s1, 1);
        s1 += __shfl_xor_sync(0xffffffffu, s1, 2);
        l0 = l0 * c0 + s0;  l1 = l1 * c1 + s1;
        m0 = mn0;  m1 = mn1;
        #pragma unroll
        for (int nf = 0; nf < 8; nf++) {
            ofr[nf][0] *= c0; ofr[nf][1] *= c0;
            ofr[nf][2] *= c1; ofr[nf][3] *= c1;
        }
        __syncwarp();

        CP_ASYNC_WAIT0();          // V arrived
        __syncthreads();

        // O += P V   (4 k16 steps over kv=64)
        #pragma unroll
        for (int ks = 0; ks < 4; ks++) {
            uint32_t afr[4], bfr[4][4];
            ldsm_x4(afr, prow + ks * 32);
            #pragma unroll
            for (int bf = 0; bf < 4; bf++)
                ldsm_x4(bfr[bf], sm_v + (uint32_t)(16 * bf + lr) * ATT_ROWB
                                   + ks * 32 + lh);
            #pragma unroll
            for (int nf = 0; nf < 8; nf++)
                mma_f16(ofr[nf], afr,
                        bfr[nf >> 1][nf & 1], bfr[nf >> 1][2 + (nf & 1)]);
        }
        __syncthreads();
    }

    // Normalize + store fp16 (feeds Wo GEMM)
    float i0 = 1.f / l0, i1 = 1.f / l1;
    __half* Og = O + ((size_t)b * S_ + q0) * D_ + h * DH_;
    int r0 = 16 * wid + qr;
    #pragma unroll
    for (int nf = 0; nf < 8; nf++) {
        int cc = 8 * nf + qc;
        *(uint32_t*)&Og[(size_t)r0 * D_ + cc] =
            pack_f16(ofr[nf][0] * i0, ofr[nf][1] * i0);
        *(uint32_t*)&Og[(size_t)(r0 + 8) * D_ + cc] =
            pack_f16(ofr[nf][2] * i1, ofr[nf][3] * i1);
    }
}

// ---------------------------------------------------------------------------
// Launch
// ---------------------------------------------------------------------------
extern "C" void kernel_launch(void* const* d_in, const int* in_sizes, int n_in,
                              void* d_out, int out_size)
{
    (void)in_sizes; (void)n_in; (void)out_size;
    const float* x    = (const float*)d_in[0];
    const int*   lidx = (const int*)  d_in[1];
    const float* Wq = (const float*)d_in[2];  const float* bq = (const float*)d_in[3];
    const float* Wk = (const float*)d_in[4];  const float* bk = (const float*)d_in[5];
    const float* Wv = (const float*)d_in[6];  const float* bv = (const float*)d_in[7];
    const float* Wo = (const float*)d_in[8];  const float* bo = (const float*)d_in[9];
    const float* s1 = (const float*)d_in[10]; const float* b1n = (const float*)d_in[11];
    const float* s2 = (const float*)d_in[12]; const float* b2n = (const float*)d_in[13];
    const float* W1 = (const float*)d_in[14]; const float* bf1 = (const float*)d_in[15];
    const float* W2 = (const float*)d_in[16]; const float* bf2 = (const float*)d_in[17];
    float* out = (float*)d_out;

    __half *h_, *q_, *k_, *vT_, *at_, *ff_;
    __half *wqT, *wkT, *wvT, *woT, *w1T, *w2T;
    cudaGetSymbolAddress((void**)&h_,  g_h);
    cudaGetSymbolAddress((void**)&q_,  g_q);
    cudaGetSymbolAddress((void**)&k_,  g_k);
    cudaGetSymbolAddress((void**)&vT_, g_vT);
    cudaGetSymbolAddress((void**)&at_, g_attn);
    cudaGetSymbolAddress((void**)&ff_, g_ffn);
    cudaGetSymbolAddress((void**)&wqT, g_WqT);
    cudaGetSymbolAddress((void**)&wkT, g_WkT);
    cudaGetSymbolAddress((void**)&wvT, g_WvT);
    cudaGetSymbolAddress((void**)&woT, g_WoT);
    cudaGetSymbolAddress((void**)&w1T, g_W1T);
    cudaGetSymbolAddress((void**)&w2T, g_W2T);

    cudaFuncSetAttribute(attention_mma,
                         cudaFuncAttributeMaxDynamicSharedMemorySize, ATT_SMEM);
    cudaFuncSetAttribute(gemm_qkv,
                         cudaFuncAttributeMaxDynamicSharedMemorySize, GEMM_SMEM);
    cudaFuncSetAttribute(gemm_mma<0,1,0>,
                         cudaFuncAttributeMaxDynamicSharedMemorySize, GEMM_SMEM);
    cudaFuncSetAttribute(gemm_mma<1,0,1>,
                         cudaFuncAttributeMaxDynamicSharedMemorySize, GEMM_SMEM);

    dim3 gD(D_ / 128, S_ / 128, B_);
    dim3 gF(F_ / 128, S_ / 128, B_);

    // LN1 + Wq/Wk/Wv transpose+round (fused; 16384 LN CTAs + 1536 transpose)
    ln1_fused_kernel<<<B_ * S_ + 1536, 256>>>(x, s1, b1n, lidx, h_,
                                              Wq, Wk, Wv, wqT, wkT, wvT);
    // Fused QKV GEMM + Wo/W1/W2 transpose CTAs (hidden under compute)
    gemm_qkv<<<dim3(60, S_ / 128, B_), 256, GEMM_SMEM>>>(
        h_, wqT, wkT, wvT, bq, bk, bv, lidx, q_, k_, vT_,
        Wo, W1, W2, woT, w1T, w2T);
    // Attention (fp16 tensor-core)
    attention_mma<<<dim3(S_ / 128, H_, B_), 256, ATT_SMEM>>>(q_, k_, vT_, at_);
    // O-proj + residual(x) -> out (fp32)
    gemm_mma<0,1,0><<<gD, 256, GEMM_SMEM>>>(at_, woT, bo, lidx, x, out,
                                            S_, D_, D_);
    // LN2 -> h (fp16)
    ln_kernel<<<B_ * S_, 256>>>(out, s2, b2n, lidx, h_);
    // FFN1 + GELU -> ff (fp16)
    gemm_mma<1,0,1><<<gF, 256, GEMM_SMEM>>>(h_, w1T, bf1, lidx, nullptr, ff_,
                                            S_, D_, F_);
    // FFN2 + residual(out) -> final (fp32)
    gemm_mma<0,1,0><<<gD, 256, GEMM_SMEM>>>(ff_, w2T, bf2, lidx, out, out,
                                            S_, F_, D_);
}